// round 6
// baseline (speedup 1.0000x reference)
#include <cuda_runtime.h>
#include <cuda_bf16.h>
#include <cstdint>
#include <math.h>

// ---------------- problem constants ----------------
constexpr int NB  = 256;
constexpr int NIN = 64;
constexpr int NH  = 768;
constexpr int NL  = 4;
constexpr int NP  = 8;
#define EPSV 1e-5f

typedef unsigned long long u64;
typedef uint32_t u32;

// ---------------- device scratch ----------------
__device__ float          g_h[NB * NH];                 // residual stream
__device__ __nv_bfloat16  g_ahi[NB * NH];               // hn hi (bf16)
__device__ __nv_bfloat16  g_alo[NB * NH];               // hn lo (bf16)
__device__ float          g_tropT[NL * NH * NH];        // [l][i][o]
__device__ __nv_bfloat16  g_wT_hi[2 * NL * NH * NH];    // [mat*NL+l][o][i]
__device__ __nv_bfloat16  g_wT_lo[2 * NL * NH * NH];
__device__ float          g_part[6 * NB * NH];          // [(kp*2+mat)][row][o]
// replay-idempotent: atomic max/min over identical inputs -> identical values each run
__device__ unsigned       g_wmax_enc[NL] = {0u, 0u, 0u, 0u};
__device__ unsigned       g_wmin_enc[NL] = {0xFFFFFFFFu, 0xFFFFFFFFu, 0xFFFFFFFFu, 0xFFFFFFFFu};
__device__ float          g_cand_val[NB * NH];
__device__ int            g_cand_idx[NB * NH];
__device__ int            g_cand_cnt[NB];

// order-preserving float <-> uint
__device__ __forceinline__ unsigned f2ord(float f) {
    unsigned u = __float_as_uint(f);
    return (u & 0x80000000u) ? ~u : (u | 0x80000000u);
}
__device__ __forceinline__ float ord2f(unsigned u) {
    return __uint_as_float((u & 0x80000000u) ? (u ^ 0x80000000u) : ~u);
}
__device__ __forceinline__ float sigmoidf_(float x) { return 1.0f / (1.0f + __expf(-x)); }

__device__ __forceinline__ u32 smem_u32(const void* p) {
    u32 a;
    asm("{ .reg .u64 t; cvta.to.shared.u64 t, %1; cvt.u32.u64 %0, t; }" : "=r"(a) : "l"(p));
    return a;
}
__device__ __forceinline__ void ldsm4(u32& r0, u32& r1, u32& r2, u32& r3, u32 a) {
    asm volatile("ldmatrix.sync.aligned.m8n8.x4.shared.b16 {%0,%1,%2,%3}, [%4];"
                 : "=r"(r0), "=r"(r1), "=r"(r2), "=r"(r3) : "r"(a));
}
__device__ __forceinline__ void mma16816(float* c, u32 a0, u32 a1, u32 a2, u32 a3, u32 b0, u32 b1) {
    asm volatile("mma.sync.aligned.m16n8k16.row.col.f32.bf16.bf16.f32 "
                 "{%0,%1,%2,%3}, {%4,%5,%6,%7}, {%8,%9}, {%0,%1,%2,%3};"
                 : "+f"(c[0]), "+f"(c[1]), "+f"(c[2]), "+f"(c[3])
                 : "r"(a0), "r"(a1), "r"(a2), "r"(a3), "r"(b0), "r"(b1));
}
__device__ __forceinline__ void cpa16(u32 dst, const void* src) {
    asm volatile("cp.async.cg.shared.global [%0], [%1], 16;" :: "r"(dst), "l"(src));
}
#define CPA_COMMIT() asm volatile("cp.async.commit_group;" ::: "memory")
#define CPA_WAIT(n)  asm volatile("cp.async.wait_group %0;" :: "n"(n) : "memory")

// ---------------- kernel 1: prep (trop transpose+minmax  |  weight transpose+bf16 hi/lo) ----------------
__global__ void k_prep(const float* __restrict__ tw,
                       const float* __restrict__ cls_w, const float* __restrict__ gate_w) {
    __shared__ float tile[32][33];
    int z  = blockIdx.z;
    int i0 = blockIdx.x * 32, o0 = blockIdx.y * 32;
    if (z < NL) {
        int l = z;
        const float* src = tw + (size_t)l * NH * NH;     // [o][i]
        float*       dst = g_tropT + (size_t)l * NH * NH;
        float lmax = -1e30f, lmin = 1e30f;
#pragma unroll
        for (int k = 0; k < 32; k += 8) {
            float v = src[(size_t)(o0 + threadIdx.y + k) * NH + (i0 + threadIdx.x)];
            tile[threadIdx.y + k][threadIdx.x] = v;
            lmax = fmaxf(lmax, v); lmin = fminf(lmin, v);
        }
        __syncthreads();
#pragma unroll
        for (int k = 0; k < 32; k += 8)
            dst[(size_t)(i0 + threadIdx.y + k) * NH + (o0 + threadIdx.x)] = tile[threadIdx.x][threadIdx.y + k];

        for (int off = 16; off > 0; off >>= 1) {
            lmax = fmaxf(lmax, __shfl_down_sync(0xffffffffu, lmax, off));
            lmin = fminf(lmin, __shfl_down_sync(0xffffffffu, lmin, off));
        }
        __shared__ float smax[8], smin[8];
        if (threadIdx.x == 0) { smax[threadIdx.y] = lmax; smin[threadIdx.y] = lmin; }
        __syncthreads();
        if (threadIdx.y == 0 && threadIdx.x == 0) {
            float bm = smax[0], bn = smin[0];
            for (int w = 1; w < 8; w++) { bm = fmaxf(bm, smax[w]); bn = fminf(bn, smin[w]); }
            atomicMax(&g_wmax_enc[l], f2ord(bm));
            atomicMin(&g_wmin_enc[l], f2ord(bn));
        }
    } else {
        int zz = z - NL;                  // zz = mat*NL + l
        int mat = zz >> 2, l = zz & 3;
        const float* src = (mat ? gate_w : cls_w) + (size_t)l * NH * NH;   // [i][o]
#pragma unroll
        for (int k = 0; k < 32; k += 8)
            tile[threadIdx.y + k][threadIdx.x] = src[(size_t)(i0 + threadIdx.y + k) * NH + (o0 + threadIdx.x)];
        __syncthreads();
#pragma unroll
        for (int k = 0; k < 32; k += 8) {
            float v = tile[threadIdx.x][threadIdx.y + k];
            __nv_bfloat16 hi = __float2bfloat16(v);
            __nv_bfloat16 lo = __float2bfloat16(v - __bfloat162float(hi));
            size_t idx = ((size_t)zz * NH + (o0 + threadIdx.y + k)) * NH + (i0 + threadIdx.x);
            g_wT_hi[idx] = hi;
            g_wT_lo[idx] = lo;
        }
    }
}

// ---------------- shared block routine: LayerNorm + candidate extraction ----------------
__device__ __forceinline__ void ln_and_candidates(
    int row, int t, float v0, float v1, float v2,
    const float* __restrict__ ln_g, const float* __restrict__ ln_b, int lc)
{
    __shared__ float r1[8], r2[8], bc[2];
    __shared__ int cnt;
    int lane = t & 31, wid = t >> 5;
    float s = v0 + v1 + v2;
    float q = v0 * v0 + v1 * v1 + v2 * v2;
    for (int off = 16; off > 0; off >>= 1) {
        s += __shfl_down_sync(0xffffffffu, s, off);
        q += __shfl_down_sync(0xffffffffu, q, off);
    }
    if (lane == 0) { r1[wid] = s; r2[wid] = q; }
    __syncthreads();
    if (t == 0) {
        float ss = 0.f, qq = 0.f;
        for (int w = 0; w < 8; w++) { ss += r1[w]; qq += r2[w]; }
        float mu  = ss / (float)NH;
        float var = fmaxf(qq / (float)NH - mu * mu, 0.f);
        bc[0] = mu; bc[1] = rsqrtf(var + EPSV);
        cnt = 0;
    }
    __syncthreads();
    float mu = bc[0], inv = bc[1];
    const float* G  = ln_g + lc * NH;
    const float* Bv = ln_b + lc * NH;
    float h0 = (v0 - mu) * inv * G[t]       + Bv[t];
    float h1 = (v1 - mu) * inv * G[t + 256] + Bv[t + 256];
    float h2 = (v2 - mu) * inv * G[t + 512] + Bv[t + 512];
#pragma unroll
    for (int k = 0; k < 3; k++) {
        int j = t + k * 256;
        float hv = (k == 0 ? h0 : (k == 1 ? h1 : h2));
        __nv_bfloat16 hi = __float2bfloat16(hv);
        g_ahi[row * NH + j] = hi;
        g_alo[row * NH + j] = __float2bfloat16(hv - __bfloat162float(hi));
    }
    float m = fmaxf(h0, fmaxf(h1, h2));
    for (int off = 16; off > 0; off >>= 1) m = fmaxf(m, __shfl_down_sync(0xffffffffu, m, off));
    if (lane == 0) r1[wid] = m;
    __syncthreads();
    if (t == 0) {
        float mm = r1[0];
        for (int w = 1; w < 8; w++) mm = fmaxf(mm, r1[w]);
        bc[0] = mm;
    }
    __syncthreads();
    // EXACT pruning: i can win max_i(hn[i]+W[o,i]) only if hn[i] >= rowmax - (Wmax-Wmin)
    float spread = ord2f(g_wmax_enc[lc]) - ord2f(g_wmin_enc[lc]);
    float tau = bc[0] - spread - 1e-6f;
    if (h0 >= tau) { int p = atomicAdd(&cnt, 1); g_cand_val[row * NH + p] = h0; g_cand_idx[row * NH + p] = t; }
    if (h1 >= tau) { int p = atomicAdd(&cnt, 1); g_cand_val[row * NH + p] = h1; g_cand_idx[row * NH + p] = t + 256; }
    if (h2 >= tau) { int p = atomicAdd(&cnt, 1); g_cand_val[row * NH + p] = h2; g_cand_idx[row * NH + p] = t + 512; }
    __syncthreads();
    if (t == 0) g_cand_cnt[row] = cnt;
}

// ---------------- kernel 2: input GEMM, smem-tiled ----------------
__global__ void __launch_bounds__(256) k_input(
    const float* __restrict__ x, const float* __restrict__ w_in, const float* __restrict__ b_in)
{
    __shared__ float ws[NIN * 128];    // 32 KB
    __shared__ float xs[8 * NIN];      // 2 KB
    int jc = blockIdx.x * 128, r0 = blockIdx.y * 8;
    int t = threadIdx.x;
#pragma unroll
    for (int i = 0; i < 32; i++) {
        int idx = t + i * 256;
        int ik = idx >> 7, j = idx & 127;
        ws[idx] = w_in[ik * NH + jc + j];
    }
#pragma unroll
    for (int i = 0; i < 2; i++) {
        int idx = t + i * 256;
        int r = idx >> 6, ik = idx & 63;
        xs[idx] = x[(r0 + r) * NIN + ik];
    }
    __syncthreads();

    int j = t & 127, rh = t >> 7;
    float acc0, acc1, acc2, acc3;
    acc0 = acc1 = acc2 = acc3 = b_in[jc + j];
    const float* xr = xs + rh * 4 * NIN;
#pragma unroll 8
    for (int i = 0; i < NIN; i++) {
        float w = ws[i * 128 + j];
        acc0 += xr[i] * w;
        acc1 += xr[NIN + i] * w;
        acc2 += xr[2 * NIN + i] * w;
        acc3 += xr[3 * NIN + i] * w;
    }
    int rb = r0 + rh * 4;
    g_h[(rb + 0) * NH + jc + j] = acc0;
    g_h[(rb + 1) * NH + jc + j] = acc1;
    g_h[(rb + 2) * NH + jc + j] = acc2;
    g_h[(rb + 3) * NH + jc + j] = acc3;
}

// ---------------- kernel 3: LN + candidates for layer lc ----------------
__global__ void k_lnc(const float* __restrict__ ln_g, const float* __restrict__ ln_b, int lc) {
    int row = blockIdx.x, t = threadIdx.x;
    float v0 = g_h[row * NH + t];
    float v1 = g_h[row * NH + t + 256];
    float v2 = g_h[row * NH + t + 512];
    ln_and_candidates(row, t, v0, v1, v2, ln_g, ln_b, lc);
}

// ---------------- kernel 4: dual GEMM, mma.sync bf16 hi/lo, cp.async 4-stage, 288 CTAs ----------------
// grid (24, 4, 3): x = n-tile (64 over 2*768), y = m-tile (64), z = pass (hh/hl/lh).
// 128 threads = 4 warps over m; warp tile 16m x 64n.
constexpr int LDS_PAD = 72;                        // bf16/row (144 B) — conflict-free ldmatrix
constexpr int A_ELE = 64 * LDS_PAD;                // 4608
constexpr int B_ELE = 64 * LDS_PAD;                // 4608
constexpr int BUF_BYTES = (A_ELE + B_ELE) * 2;     // 18432
constexpr int STAGES = 4;
constexpr int SMEM_GEMM = STAGES * BUF_BYTES;      // 73728

__global__ void __launch_bounds__(128) k_gemm_mma(int l) {
    extern __shared__ __nv_bfloat16 sm[];
    u32 sbase = smem_u32(sm);
    int t = threadIdx.x, lane = t & 31, mw = t >> 5;
    int nb = blockIdx.x;
    int m0 = blockIdx.y * 64;
    int kp = blockIdx.z;                  // 0: Ahi*Bhi, 1: Ahi*Blo, 2: Alo*Bhi
    int mat = nb / 12;
    int o0 = (nb % 12) * 64;

    const __nv_bfloat16* As = (kp < 2 ? g_ahi : g_alo) + (size_t)m0 * NH;
    const __nv_bfloat16* Bs = (kp == 1 ? g_wT_lo : g_wT_hi) + ((size_t)(mat * NL + l) * NH + o0) * NH;

    float acc[8][4];
#pragma unroll
    for (int i = 0; i < 8; i++)
#pragma unroll
        for (int j = 0; j < 4; j++) acc[i][j] = 0.f;

    int ur = t >> 3, uc = t & 7;          // 16 rows x 8 16B-cols per 128 threads

#define ISSUE_CHUNK(c, s)                                                           \
    {                                                                               \
        int kc = (c) * 64;                                                          \
        u32 abase = sbase + (s) * BUF_BYTES;                                        \
        u32 bbase = abase + A_ELE * 2;                                              \
        _Pragma("unroll")                                                           \
        for (int i = 0; i < 4; i++) {                                               \
            int r = ur + i * 16;                                                    \
            cpa16(abase + (u32)(r * LDS_PAD + uc * 8) * 2,                          \
                  As + (size_t)r * NH + kc + uc * 8);                               \
        }                                                                           \
        _Pragma("unroll")                                                           \
        for (int i = 0; i < 4; i++) {                                               \
            int r = ur + i * 16;                                                    \
            cpa16(bbase + (u32)(r * LDS_PAD + uc * 8) * 2,                          \
                  Bs + (size_t)r * NH + kc + uc * 8);                               \
        }                                                                           \
        CPA_COMMIT();                                                               \
    }

    // ldmatrix per-thread offsets
    int ar = (lane & 7) + ((lane >> 3) & 1) * 8;
    int ac = (lane >> 4) * 8;
    u32 a_off = (u32)((mw * 16 + ar) * LDS_PAD + ac) * 2;
    int bn = (lane & 7) + ((lane >> 4) & 1) * 8;
    int bk = ((lane >> 3) & 1) * 8;
    u32 b_off = (u32)(bn * LDS_PAD + bk) * 2;

    ISSUE_CHUNK(0, 0);
    ISSUE_CHUNK(1, 1);
    ISSUE_CHUNK(2, 2);

    for (int ci = 0; ci < 12; ci++) {
        if (ci < 10)      { CPA_WAIT(2); }
        else if (ci == 10){ CPA_WAIT(1); }
        else              { CPA_WAIT(0); }
        __syncthreads();
        int s = ci & 3;
        u32 abase = sbase + (u32)s * BUF_BYTES + a_off;
        u32 bbase = sbase + (u32)s * BUF_BYTES + A_ELE * 2 + b_off;
#pragma unroll
        for (int ks = 0; ks < 4; ks++) {
            u32 a0, a1, a2, a3;
            ldsm4(a0, a1, a2, a3, abase + ks * 32);
#pragma unroll
            for (int nt2 = 0; nt2 < 4; nt2++) {
                u32 r0, r1, r2, r3;
                ldsm4(r0, r1, r2, r3, bbase + (u32)(nt2 * 16 * LDS_PAD) * 2 + ks * 32);
                mma16816(acc[nt2 * 2],     a0, a1, a2, a3, r0, r1);
                mma16816(acc[nt2 * 2 + 1], a0, a1, a2, a3, r2, r3);
            }
        }
        if (ci + 3 < 12) ISSUE_CHUNK(ci + 3, (ci + 3) & 3);
    }
#undef ISSUE_CHUNK

    // store partials
    int r = lane >> 2, c2 = (lane & 3) * 2;
#pragma unroll
    for (int nt = 0; nt < 8; nt++) {
        int o = o0 + nt * 8 + c2;
        float* dst = g_part + ((size_t)(kp * 2 + mat) * NB + m0 + mw * 16 + r) * NH + o;
        *(float2*)dst = make_float2(acc[nt][0], acc[nt][1]);
        *(float2*)(dst + (size_t)8 * NH) = make_float2(acc[nt][2], acc[nt][3]);
    }
}

// ---------------- kernel 5: j-tiled epilogue ----------------
// grid (6 j-tiles of 128, 32 row-chunks of 8), 256 threads = 128 j x 2 row-halves (4 rows each).
// LF tables staged in smem in [p][j] layout (conflict-free), loaded once per block.
constexpr int EJT = 128;
constexpr int ERB = 8;

__global__ void __launch_bounds__(256) k_epi2(int l,
    const float* __restrict__ cls_b,  const float* __restrict__ gate_b,
    const float* __restrict__ trop_b,
    const float* __restrict__ lf_amax, const float* __restrict__ lf_bmax,
    const float* __restrict__ lf_amin, const float* __restrict__ lf_bmin,
    const float* __restrict__ lf_alpha)
{
    __shared__ float s_am[NP * EJT], s_bm[NP * EJT], s_an[NP * EJT], s_bn[NP * EJT];
    __shared__ float s_tb[EJT], s_cb[EJT], s_gb[EJT], s_al[EJT];
    __shared__ float scv[ERB * 64];
    __shared__ int   sci[ERB * 64];
    __shared__ int   scnt[ERB];

    int j0 = blockIdx.x * EJT, r0 = blockIdx.y * ERB;
    int t = threadIdx.x;

    // LF load + transpose to [p][j]: thread t reads float4 = (j = t>>1, p-half = t&1)
    {
        int jj = t >> 1, ph = (t & 1) * 4;
        const float4* AM = (const float4*)(lf_amax + ((size_t)l * NH + j0) * NP);
        const float4* BM = (const float4*)(lf_bmax + ((size_t)l * NH + j0) * NP);
        const float4* AN = (const float4*)(lf_amin + ((size_t)l * NH + j0) * NP);
        const float4* BN = (const float4*)(lf_bmin + ((size_t)l * NH + j0) * NP);
        float4 am = AM[t], bm = BM[t], an = AN[t], bn = BN[t];
        s_am[(ph + 0) * EJT + jj] = am.x; s_am[(ph + 1) * EJT + jj] = am.y;
        s_am[(ph + 2) * EJT + jj] = am.z; s_am[(ph + 3) * EJT + jj] = am.w;
        s_bm[(ph + 0) * EJT + jj] = bm.x; s_bm[(ph + 1) * EJT + jj] = bm.y;
        s_bm[(ph + 2) * EJT + jj] = bm.z; s_bm[(ph + 3) * EJT + jj] = bm.w;
        s_an[(ph + 0) * EJT + jj] = an.x; s_an[(ph + 1) * EJT + jj] = an.y;
        s_an[(ph + 2) * EJT + jj] = an.z; s_an[(ph + 3) * EJT + jj] = an.w;
        s_bn[(ph + 0) * EJT + jj] = bn.x; s_bn[(ph + 1) * EJT + jj] = bn.y;
        s_bn[(ph + 2) * EJT + jj] = bn.z; s_bn[(ph + 3) * EJT + jj] = bn.w;
    }
    if (t < EJT) {
        s_tb[t] = trop_b[l * NH + j0 + t];
        s_cb[t] = cls_b[l * NH + j0 + t];
        s_gb[t] = gate_b[l * NH + j0 + t];
        s_al[t] = lf_alpha[l * NH + j0 + t];
    }
    {
        int rr = t >> 5, cc = t & 31;
        int cn = g_cand_cnt[r0 + rr];
        if (cn > 64) cn = 64;
        if (cc == 0) scnt[rr] = cn;
        for (int c = cc; c < cn; c += 32) {
            scv[rr * 64 + c] = g_cand_val[(r0 + rr) * NH + c];
            sci[rr * 64 + c] = g_cand_idx[(r0 + rr) * NH + c];
        }
    }
    __syncthreads();

    int jl = t & 127, rh = t >> 7;
    int j = j0 + jl;
    const float* tT = g_tropT + (size_t)l * NH * NH;

#pragma unroll
    for (int ri = 0; ri < 4; ri++) {
        int rl = rh * 4 + ri;
        int row = r0 + rl;
        float c = g_part[((size_t)0 * NB + row) * NH + j]
                + g_part[((size_t)2 * NB + row) * NH + j]
                + g_part[((size_t)4 * NB + row) * NH + j] + s_cb[jl];
        float g = g_part[((size_t)1 * NB + row) * NH + j]
                + g_part[((size_t)3 * NB + row) * NH + j]
                + g_part[((size_t)5 * NB + row) * NH + j] + s_gb[jl];

        float tm = -1e30f;
        int cn = scnt[rl];
        for (int cc = 0; cc < cn; cc++)
            tm = fmaxf(tm, scv[rl * 64 + cc] + tT[(size_t)sci[rl * 64 + cc] * NH + j]);
        float tt = tm + s_tb[jl];

        float fmx = -1e30f, fmn = 1e30f;
#pragma unroll
        for (int p = 0; p < NP; p++) {
            fmx = fmaxf(fmx, tt * s_am[p * EJT + jl] + s_bm[p * EJT + jl]);
            fmn = fminf(fmn, tt * s_an[p * EJT + jl] + s_bn[p * EJT + jl]);
        }
        float a_ = sigmoidf_(s_al[jl]);
        float trop_out = a_ * fmx + (1.0f - a_) * fmn;
        float cls_out = 0.5f * c * (1.0f + erff(c * 0.70710678118654752f));
        float gg = sigmoidf_(g);
        g_h[(size_t)row * NH + j] += gg * trop_out + (1.0f - gg) * cls_out;
    }
}

// ---------------- kernel 6: final LN + head ----------------
__global__ void k_final(const float* __restrict__ out_g, const float* __restrict__ out_b,
                        const float* __restrict__ head_w, const float* __restrict__ head_b,
                        float* __restrict__ out)
{
    __shared__ float r1[8], r2[8], bc[2];
    int row = blockIdx.x, t = threadIdx.x, lane = t & 31, wid = t >> 5;
    float v0 = g_h[row * NH + t];
    float v1 = g_h[row * NH + t + 256];
    float v2 = g_h[row * NH + t + 512];
    float s = v0 + v1 + v2;
    float q = v0 * v0 + v1 * v1 + v2 * v2;
    for (int off = 16; off > 0; off >>= 1) {
        s += __shfl_down_sync(0xffffffffu, s, off);
        q += __shfl_down_sync(0xffffffffu, q, off);
    }
    if (lane == 0) { r1[wid] = s; r2[wid] = q; }
    __syncthreads();
    if (t == 0) {
        float ss = 0.f, qq = 0.f;
        for (int w = 0; w < 8; w++) { ss += r1[w]; qq += r2[w]; }
        float mu  = ss / (float)NH;
        float var = fmaxf(qq / (float)NH - mu * mu, 0.f);
        bc[0] = mu; bc[1] = rsqrtf(var + EPSV);
    }
    __syncthreads();
    float mu = bc[0], inv = bc[1];
    float d = ((v0 - mu) * inv * out_g[t]       + out_b[t])       * head_w[t]
            + ((v1 - mu) * inv * out_g[t + 256] + out_b[t + 256]) * head_w[t + 256]
            + ((v2 - mu) * inv * out_g[t + 512] + out_b[t + 512]) * head_w[t + 512];
    for (int off = 16; off > 0; off >>= 1) d += __shfl_down_sync(0xffffffffu, d, off);
    __syncthreads();
    if (lane == 0) r1[wid] = d;
    __syncthreads();
    if (t == 0) {
        float dd = 0.f;
        for (int w = 0; w < 8; w++) dd += r1[w];
        out[row] = dd + head_b[0];
    }
}

// ---------------- launch ----------------
extern "C" void kernel_launch(void* const* d_in, const int* in_sizes, int n_in,
                              void* d_out, int out_size) {
    const float* x        = (const float*)d_in[0];
    const float* w_in     = (const float*)d_in[1];
    const float* b_in     = (const float*)d_in[2];
    const float* ln_g     = (const float*)d_in[3];
    const float* ln_b     = (const float*)d_in[4];
    const float* trop_w   = (const float*)d_in[5];
    const float* trop_b   = (const float*)d_in[6];
    const float* lf_amax  = (const float*)d_in[7];
    const float* lf_bmax  = (const float*)d_in[8];
    const float* lf_amin  = (const float*)d_in[9];
    const float* lf_bmin  = (const float*)d_in[10];
    const float* lf_alpha = (const float*)d_in[11];
    const float* gate_w   = (const float*)d_in[12];
    const float* gate_b   = (const float*)d_in[13];
    const float* cls_w    = (const float*)d_in[14];
    const float* cls_b    = (const float*)d_in[15];
    const float* out_g    = (const float*)d_in[16];
    const float* out_b    = (const float*)d_in[17];
    const float* head_w   = (const float*)d_in[18];
    const float* head_b   = (const float*)d_in[19];
    float* out = (float*)d_out;

    // one-time host-side resources (no device memory)
    static cudaStream_t s_side = nullptr;
    static cudaEvent_t  ev_fork = nullptr, ev_join = nullptr;
    if (!s_side) {
        cudaStreamCreateWithFlags(&s_side, cudaStreamNonBlocking);
        cudaEventCreateWithFlags(&ev_fork, cudaEventDisableTiming);
        cudaEventCreateWithFlags(&ev_join, cudaEventDisableTiming);
        cudaFuncSetAttribute(k_gemm_mma, cudaFuncAttributeMaxDynamicSharedMemorySize, SMEM_GEMM);
    }

    // fork: prep runs concurrently with input GEMM + first LN
    cudaEventRecord(ev_fork, 0);
    cudaStreamWaitEvent(s_side, ev_fork, 0);
    k_prep<<<dim3(NH / 32, NH / 32, NL + 2 * NL), dim3(32, 8), 0, s_side>>>(trop_w, cls_w, gate_w);
    cudaEventRecord(ev_join, s_side);

    k_input<<<dim3(6, 32), 256>>>(x, w_in, b_in);
    k_lnc<<<NB, 256>>>(ln_g, ln_b, 0);
    cudaStreamWaitEvent(0, ev_join, 0);

    for (int l = 0; l < NL; l++) {
        k_gemm_mma<<<dim3(24, 4, 3), 128, SMEM_GEMM>>>(l);
        k_epi2<<<dim3(NH / EJT, NB / ERB), 256>>>(l, cls_b, gate_b, trop_b,
                                                  lf_amax, lf_bmax, lf_amin, lf_bmin, lf_alpha);
        if (l < NL - 1) {
            k_lnc<<<NB, 256>>>(ln_g, ln_b, l + 1);
        } else {
            k_final<<<NB, 256>>>(out_g, out_b, head_w, head_b, out);
        }
    }
}

// round 9
// speedup vs baseline: 1.7273x; 1.7273x over previous
#include <cuda_runtime.h>
#include <cuda_bf16.h>
#include <cstdint>
#include <math.h>

// ---------------- problem constants ----------------
constexpr int NB  = 256;
constexpr int NIN = 64;
constexpr int NH  = 768;
constexpr int NL  = 4;
constexpr int NP  = 8;
#define EPSV 1e-5f

typedef unsigned long long u64;
typedef uint32_t u32;

// ---------------- device scratch ----------------
__device__ float          g_h[NB * NH];                 // residual stream
__device__ __nv_bfloat16  g_ahi[NB * NH];               // hn hi (bf16)
__device__ __nv_bfloat16  g_alo[NB * NH];               // hn lo (bf16)
__device__ float          g_tropT[NL * NH * NH];        // [l][i][o]
__device__ __nv_bfloat16  g_wT_hi[2 * NL * NH * NH];    // [mat*NL+l][o][i]
__device__ __nv_bfloat16  g_wT_lo[2 * NL * NH * NH];
__device__ float          g_part[12 * NB * NH];         // [(kp*2+mat)][row][o], kp in 0..5
// replay-idempotent: atomic max/min over identical inputs -> identical values each run
__device__ unsigned       g_wmax_enc[NL] = {0u, 0u, 0u, 0u};
__device__ unsigned       g_wmin_enc[NL] = {0xFFFFFFFFu, 0xFFFFFFFFu, 0xFFFFFFFFu, 0xFFFFFFFFu};
__device__ float          g_cand_val[NB * NH];
__device__ int            g_cand_idx[NB * NH];
__device__ int            g_cand_cnt[NB];

// order-preserving float <-> uint
__device__ __forceinline__ unsigned f2ord(float f) {
    unsigned u = __float_as_uint(f);
    return (u & 0x80000000u) ? ~u : (u | 0x80000000u);
}
__device__ __forceinline__ float ord2f(unsigned u) {
    return __uint_as_float((u & 0x80000000u) ? (u ^ 0x80000000u) : ~u);
}
__device__ __forceinline__ float sigmoidf_(float x) { return 1.0f / (1.0f + __expf(-x)); }

__device__ __forceinline__ u32 smem_u32(const void* p) {
    u32 a;
    asm("{ .reg .u64 t; cvta.to.shared.u64 t, %1; cvt.u32.u64 %0, t; }" : "=r"(a) : "l"(p));
    return a;
}
__device__ __forceinline__ void ldsm4(u32& r0, u32& r1, u32& r2, u32& r3, u32 a) {
    asm volatile("ldmatrix.sync.aligned.m8n8.x4.shared.b16 {%0,%1,%2,%3}, [%4];"
                 : "=r"(r0), "=r"(r1), "=r"(r2), "=r"(r3) : "r"(a));
}
__device__ __forceinline__ void mma16816(float* c, u32 a0, u32 a1, u32 a2, u32 a3, u32 b0, u32 b1) {
    asm volatile("mma.sync.aligned.m16n8k16.row.col.f32.bf16.bf16.f32 "
                 "{%0,%1,%2,%3}, {%4,%5,%6,%7}, {%8,%9}, {%0,%1,%2,%3};"
                 : "+f"(c[0]), "+f"(c[1]), "+f"(c[2]), "+f"(c[3])
                 : "r"(a0), "r"(a1), "r"(a2), "r"(a3), "r"(b0), "r"(b1));
}
__device__ __forceinline__ void cpa16(u32 dst, const void* src) {
    asm volatile("cp.async.cg.shared.global [%0], [%1], 16;" :: "r"(dst), "l"(src));
}
#define CPA_COMMIT() asm volatile("cp.async.commit_group;" ::: "memory")
#define CPA_WAIT(n)  asm volatile("cp.async.wait_group %0;" :: "n"(n) : "memory")

// ---------------- kernel 1: prep (trop transpose+minmax  |  weight transpose+bf16 hi/lo) ----------------
__global__ void k_prep(const float* __restrict__ tw,
                       const float* __restrict__ cls_w, const float* __restrict__ gate_w) {
    __shared__ float tile[32][33];
    int z  = blockIdx.z;
    int i0 = blockIdx.x * 32, o0 = blockIdx.y * 32;
    if (z < NL) {
        int l = z;
        const float* src = tw + (size_t)l * NH * NH;     // [o][i]
        float*       dst = g_tropT + (size_t)l * NH * NH;
        float lmax = -1e30f, lmin = 1e30f;
#pragma unroll
        for (int k = 0; k < 32; k += 8) {
            float v = src[(size_t)(o0 + threadIdx.y + k) * NH + (i0 + threadIdx.x)];
            tile[threadIdx.y + k][threadIdx.x] = v;
            lmax = fmaxf(lmax, v); lmin = fminf(lmin, v);
        }
        __syncthreads();
#pragma unroll
        for (int k = 0; k < 32; k += 8)
            dst[(size_t)(i0 + threadIdx.y + k) * NH + (o0 + threadIdx.x)] = tile[threadIdx.x][threadIdx.y + k];

        for (int off = 16; off > 0; off >>= 1) {
            lmax = fmaxf(lmax, __shfl_down_sync(0xffffffffu, lmax, off));
            lmin = fminf(lmin, __shfl_down_sync(0xffffffffu, lmin, off));
        }
        __shared__ float smax[8], smin[8];
        if (threadIdx.x == 0) { smax[threadIdx.y] = lmax; smin[threadIdx.y] = lmin; }
        __syncthreads();
        if (threadIdx.y == 0 && threadIdx.x == 0) {
            float bm = smax[0], bn = smin[0];
            for (int w = 1; w < 8; w++) { bm = fmaxf(bm, smax[w]); bn = fminf(bn, smin[w]); }
            atomicMax(&g_wmax_enc[l], f2ord(bm));
            atomicMin(&g_wmin_enc[l], f2ord(bn));
        }
    } else {
        int zz = z - NL;                  // zz = mat*NL + l
        int mat = zz >> 2, l = zz & 3;
        const float* src = (mat ? gate_w : cls_w) + (size_t)l * NH * NH;   // [i][o]
#pragma unroll
        for (int k = 0; k < 32; k += 8)
            tile[threadIdx.y + k][threadIdx.x] = src[(size_t)(i0 + threadIdx.y + k) * NH + (o0 + threadIdx.x)];
        __syncthreads();
#pragma unroll
        for (int k = 0; k < 32; k += 8) {
            float v = tile[threadIdx.x][threadIdx.y + k];
            __nv_bfloat16 hi = __float2bfloat16(v);
            __nv_bfloat16 lo = __float2bfloat16(v - __bfloat162float(hi));
            size_t idx = ((size_t)zz * NH + (o0 + threadIdx.y + k)) * NH + (i0 + threadIdx.x);
            g_wT_hi[idx] = hi;
            g_wT_lo[idx] = lo;
        }
    }
}

// ---------------- shared block routine: LayerNorm + candidate extraction ----------------
__device__ __forceinline__ void ln_and_candidates(
    int row, int t, float v0, float v1, float v2,
    const float* __restrict__ ln_g, const float* __restrict__ ln_b, int lc)
{
    __shared__ float r1[8], r2[8], bc[2];
    __shared__ int cnt;
    int lane = t & 31, wid = t >> 5;
    float s = v0 + v1 + v2;
    float q = v0 * v0 + v1 * v1 + v2 * v2;
    for (int off = 16; off > 0; off >>= 1) {
        s += __shfl_down_sync(0xffffffffu, s, off);
        q += __shfl_down_sync(0xffffffffu, q, off);
    }
    if (lane == 0) { r1[wid] = s; r2[wid] = q; }
    __syncthreads();
    if (t == 0) {
        float ss = 0.f, qq = 0.f;
        for (int w = 0; w < 8; w++) { ss += r1[w]; qq += r2[w]; }
        float mu  = ss / (float)NH;
        float var = fmaxf(qq / (float)NH - mu * mu, 0.f);
        bc[0] = mu; bc[1] = rsqrtf(var + EPSV);
        cnt = 0;
    }
    __syncthreads();
    float mu = bc[0], inv = bc[1];
    const float* G  = ln_g + lc * NH;
    const float* Bv = ln_b + lc * NH;
    float h0 = (v0 - mu) * inv * G[t]       + Bv[t];
    float h1 = (v1 - mu) * inv * G[t + 256] + Bv[t + 256];
    float h2 = (v2 - mu) * inv * G[t + 512] + Bv[t + 512];
#pragma unroll
    for (int k = 0; k < 3; k++) {
        int j = t + k * 256;
        float hv = (k == 0 ? h0 : (k == 1 ? h1 : h2));
        __nv_bfloat16 hi = __float2bfloat16(hv);
        g_ahi[row * NH + j] = hi;
        g_alo[row * NH + j] = __float2bfloat16(hv - __bfloat162float(hi));
    }
    float m = fmaxf(h0, fmaxf(h1, h2));
    for (int off = 16; off > 0; off >>= 1) m = fmaxf(m, __shfl_down_sync(0xffffffffu, m, off));
    if (lane == 0) r1[wid] = m;
    __syncthreads();
    if (t == 0) {
        float mm = r1[0];
        for (int w = 1; w < 8; w++) mm = fmaxf(mm, r1[w]);
        bc[0] = mm;
    }
    __syncthreads();
    // EXACT pruning: i can win max_i(hn[i]+W[o,i]) only if hn[i] >= rowmax - (Wmax-Wmin)
    float spread = ord2f(g_wmax_enc[lc]) - ord2f(g_wmin_enc[lc]);
    float tau = bc[0] - spread - 1e-6f;
    if (h0 >= tau) { int p = atomicAdd(&cnt, 1); g_cand_val[row * NH + p] = h0; g_cand_idx[row * NH + p] = t; }
    if (h1 >= tau) { int p = atomicAdd(&cnt, 1); g_cand_val[row * NH + p] = h1; g_cand_idx[row * NH + p] = t + 256; }
    if (h2 >= tau) { int p = atomicAdd(&cnt, 1); g_cand_val[row * NH + p] = h2; g_cand_idx[row * NH + p] = t + 512; }
    __syncthreads();
    if (t == 0) g_cand_cnt[row] = cnt;
}

// ---------------- kernel 2: input GEMM, smem-tiled ----------------
__global__ void __launch_bounds__(256) k_input(
    const float* __restrict__ x, const float* __restrict__ w_in, const float* __restrict__ b_in)
{
    __shared__ float ws[NIN * 128];    // 32 KB
    __shared__ float xs[8 * NIN];      // 2 KB
    int jc = blockIdx.x * 128, r0 = blockIdx.y * 8;
    int t = threadIdx.x;
#pragma unroll
    for (int i = 0; i < 32; i++) {
        int idx = t + i * 256;
        int ik = idx >> 7, j = idx & 127;
        ws[idx] = w_in[ik * NH + jc + j];
    }
#pragma unroll
    for (int i = 0; i < 2; i++) {
        int idx = t + i * 256;
        int r = idx >> 6, ik = idx & 63;
        xs[idx] = x[(r0 + r) * NIN + ik];
    }
    __syncthreads();

    int j = t & 127, rh = t >> 7;
    float acc0, acc1, acc2, acc3;
    acc0 = acc1 = acc2 = acc3 = b_in[jc + j];
    const float* xr = xs + rh * 4 * NIN;
#pragma unroll 8
    for (int i = 0; i < NIN; i++) {
        float w = ws[i * 128 + j];
        acc0 += xr[i] * w;
        acc1 += xr[NIN + i] * w;
        acc2 += xr[2 * NIN + i] * w;
        acc3 += xr[3 * NIN + i] * w;
    }
    int rb = r0 + rh * 4;
    g_h[(rb + 0) * NH + jc + j] = acc0;
    g_h[(rb + 1) * NH + jc + j] = acc1;
    g_h[(rb + 2) * NH + jc + j] = acc2;
    g_h[(rb + 3) * NH + jc + j] = acc3;
}

// ---------------- kernel 3: LN + candidates for layer 0 ----------------
__global__ void k_ln0(const float* __restrict__ ln_g, const float* __restrict__ ln_b) {
    int row = blockIdx.x, t = threadIdx.x;
    float v0 = g_h[row * NH + t];
    float v1 = g_h[row * NH + t + 256];
    float v2 = g_h[row * NH + t + 512];
    ln_and_candidates(row, t, v0, v1, v2, ln_g, ln_b, 0);
}

// ---------------- kernel 4: dual GEMM, mma.sync bf16 hi/lo, cp.async 3-stage, K-split x6 ----------------
// grid (12, 4, 6): x = n-tile (128 over 2*768), y = m-tile (64), z = kp.
// kp: pass = kp>>1 (0 hh, 1 hl, 2 lh), k-half = kp&1 (6 chunks of 64 each).
// 288 CTAs of 256 threads -> 2 CTAs/SM (16 warps/SM). Traffic unchanged vs K-unsplit.
constexpr int LDS_PAD = 72;                        // bf16/row (144 B) — conflict-free ldmatrix
constexpr int A_ELE = 64 * LDS_PAD;                // 4608
constexpr int B_ELE = 128 * LDS_PAD;               // 9216
constexpr int BUF_BYTES = (A_ELE + B_ELE) * 2;     // 27648
constexpr int STAGES = 3;
constexpr int SMEM_GEMM = STAGES * BUF_BYTES;      // 82944 -> 2 CTAs/SM fit in 228KB

__global__ void __launch_bounds__(256) k_gemm_mma(int l) {
    extern __shared__ __nv_bfloat16 sm[];
    u32 sbase = smem_u32(sm);
    int t = threadIdx.x, lane = t & 31, w = t >> 5;
    int mw = w & 3, nw = w >> 2;
    int nb = blockIdx.x;
    int m0 = blockIdx.y * 64;
    int kp = blockIdx.z;
    int pass = kp >> 1;                   // 0: Ahi*Bhi, 1: Ahi*Blo, 2: Alo*Bhi
    int kh = kp & 1;                      // k half
    int mat = nb / 6;
    int o0 = (nb % 6) * 128;

    const __nv_bfloat16* As = (pass < 2 ? g_ahi : g_alo) + (size_t)m0 * NH;
    const __nv_bfloat16* Bs = (pass == 1 ? g_wT_lo : g_wT_hi) + ((size_t)(mat * NL + l) * NH + o0) * NH;

    float acc[8][4];
#pragma unroll
    for (int i = 0; i < 8; i++)
#pragma unroll
        for (int j = 0; j < 4; j++) acc[i][j] = 0.f;

    // per-thread cp.async source/dest decomposition (256 thr = 32 rows x 8 16B-cols)
    int ur = t >> 3, uc = t & 7;
    int cbase = kh * 6;                   // 6 chunks of 64 in this CTA's k-half

#define ISSUE_CHUNK(c, s)                                                           \
    {                                                                               \
        int kc = (c) * 64;                                                          \
        u32 abase = sbase + (s) * BUF_BYTES;                                        \
        u32 bbase = abase + A_ELE * 2;                                              \
        _Pragma("unroll")                                                           \
        for (int i = 0; i < 2; i++) {                                               \
            int r = ur + i * 32;                                                    \
            cpa16(abase + (u32)(r * LDS_PAD + uc * 8) * 2,                          \
                  As + (size_t)r * NH + kc + uc * 8);                               \
        }                                                                           \
        _Pragma("unroll")                                                           \
        for (int i = 0; i < 4; i++) {                                               \
            int r = ur + i * 32;                                                    \
            cpa16(bbase + (u32)(r * LDS_PAD + uc * 8) * 2,                          \
                  Bs + (size_t)r * NH + kc + uc * 8);                               \
        }                                                                           \
        CPA_COMMIT();                                                               \
    }

    // ldmatrix per-thread offsets
    int ar = (lane & 7) + ((lane >> 3) & 1) * 8;
    int ac = (lane >> 4) * 8;
    u32 a_off = (u32)((mw * 16 + ar) * LDS_PAD + ac) * 2;
    int bn = (lane & 7) + ((lane >> 4) & 1) * 8;
    int bk = ((lane >> 3) & 1) * 8;
    u32 b_off = (u32)((nw * 64 + bn) * LDS_PAD + bk) * 2;

    ISSUE_CHUNK(cbase + 0, 0);
    ISSUE_CHUNK(cbase + 1, 1);

    for (int ci = 0; ci < 6; ci++) {
        if (ci < 5) { CPA_WAIT(1); } else { CPA_WAIT(0); }
        __syncthreads();
        int s = ci % 3;
        u32 abase = sbase + (u32)s * BUF_BYTES + a_off;
        u32 bbase = sbase + (u32)s * BUF_BYTES + A_ELE * 2 + b_off;
#pragma unroll
        for (int ks = 0; ks < 4; ks++) {
            u32 a0, a1, a2, a3;
            ldsm4(a0, a1, a2, a3, abase + ks * 32);
#pragma unroll
            for (int nt2 = 0; nt2 < 4; nt2++) {
                u32 r0, r1, r2, r3;
                ldsm4(r0, r1, r2, r3, bbase + (u32)(nt2 * 16 * LDS_PAD) * 2 + ks * 32);
                mma16816(acc[nt2 * 2],     a0, a1, a2, a3, r0, r1);
                mma16816(acc[nt2 * 2 + 1], a0, a1, a2, a3, r2, r3);
            }
        }
        if (ci + 2 < 6) ISSUE_CHUNK(cbase + ci + 2, (ci + 2) % 3);
    }
#undef ISSUE_CHUNK

    // store partials
    int r = lane >> 2, c2 = (lane & 3) * 2;
#pragma unroll
    for (int nt = 0; nt < 8; nt++) {
        int o = o0 + nw * 64 + nt * 8 + c2;
        float* dst = g_part + ((size_t)(kp * 2 + mat) * NB + m0 + mw * 16 + r) * NH + o;
        *(float2*)dst = make_float2(acc[nt][0], acc[nt][1]);
        *(float2*)(dst + (size_t)8 * NH) = make_float2(acc[nt][2], acc[nt][3]);
    }
}

// ---------------- kernel 5: epilogue + next LN / final head ----------------
__global__ void k_epi(int l,
    const float* __restrict__ cls_b,  const float* __restrict__ gate_b,
    const float* __restrict__ trop_b,
    const float* __restrict__ lf_amax, const float* __restrict__ lf_bmax,
    const float* __restrict__ lf_amin, const float* __restrict__ lf_bmin,
    const float* __restrict__ lf_alpha,
    const float* __restrict__ ln_g,   const float* __restrict__ ln_b,
    const float* __restrict__ out_g,  const float* __restrict__ out_b,
    const float* __restrict__ head_w, const float* __restrict__ head_b,
    float* __restrict__ out)
{
    __shared__ float scv[64];
    __shared__ int   sci[64];
    int row = blockIdx.x, t = threadIdx.x;
    int cnt = g_cand_cnt[row];
    if (cnt > 64) cnt = 64;   // safety clamp (expected cnt ~ 2-6)
    for (int c = t; c < cnt; c += 256) {
        scv[c] = g_cand_val[row * NH + c];
        sci[c] = g_cand_idx[row * NH + c];
    }
    __syncthreads();

    const float* tT = g_tropT + (size_t)l * NH * NH;
    float v[3];
#pragma unroll
    for (int k = 0; k < 3; k++) {
        int j = t + k * 256;
        // fixed-order partial merge (deterministic): slots kp*2+mat, kp in 0..5
        float c = 0.f, g = 0.f;
#pragma unroll
        for (int kp = 0; kp < 6; kp++) {
            c += g_part[((size_t)(kp * 2 + 0) * NB + row) * NH + j];
            g += g_part[((size_t)(kp * 2 + 1) * NB + row) * NH + j];
        }
        c += cls_b[l * NH + j];
        g += gate_b[l * NH + j];

        float tm = -1e30f;
        for (int cc = 0; cc < cnt; cc++)
            tm = fmaxf(tm, scv[cc] + tT[(size_t)sci[cc] * NH + j]);
        float tt = tm + trop_b[l * NH + j];

        const float4* AM  = (const float4*)(lf_amax + ((size_t)l * NH + j) * NP);
        const float4* BM  = (const float4*)(lf_bmax + ((size_t)l * NH + j) * NP);
        const float4* AN  = (const float4*)(lf_amin + ((size_t)l * NH + j) * NP);
        const float4* BMN = (const float4*)(lf_bmin + ((size_t)l * NH + j) * NP);
        float fmx = -1e30f, fmn = 1e30f;
#pragma unroll
        for (int q = 0; q < 2; q++) {
            float4 am = AM[q], bm = BM[q], an = AN[q], bn = BMN[q];
            fmx = fmaxf(fmx, fmaxf(fmaxf(tt * am.x + bm.x, tt * am.y + bm.y),
                                   fmaxf(tt * am.z + bm.z, tt * am.w + bm.w)));
            fmn = fminf(fmn, fminf(fminf(tt * an.x + bn.x, tt * an.y + bn.y),
                                   fminf(tt * an.z + bn.z, tt * an.w + bn.w)));
        }
        float a_ = sigmoidf_(lf_alpha[l * NH + j]);
        float trop_out = a_ * fmx + (1.0f - a_) * fmn;
        float cls_out = 0.5f * c * (1.0f + erff(c * 0.70710678118654752f));
        float gg = sigmoidf_(g);
        v[k] = g_h[row * NH + j] + gg * trop_out + (1.0f - gg) * cls_out;
        g_h[row * NH + j] = v[k];
    }
    __syncthreads();

    if (l < NL - 1) {
        ln_and_candidates(row, t, v[0], v[1], v[2], ln_g, ln_b, l + 1);
    } else {
        __shared__ float fr1[8], fr2[8], fbc[2];
        int lane = t & 31, wid = t >> 5;
        float s = v[0] + v[1] + v[2];
        float q = v[0] * v[0] + v[1] * v[1] + v[2] * v[2];
        for (int off = 16; off > 0; off >>= 1) {
            s += __shfl_down_sync(0xffffffffu, s, off);
            q += __shfl_down_sync(0xffffffffu, q, off);
        }
        if (lane == 0) { fr1[wid] = s; fr2[wid] = q; }
        __syncthreads();
        if (t == 0) {
            float ss = 0.f, qq = 0.f;
            for (int w = 0; w < 8; w++) { ss += fr1[w]; qq += fr2[w]; }
            float mu  = ss / (float)NH;
            float var = fmaxf(qq / (float)NH - mu * mu, 0.f);
            fbc[0] = mu; fbc[1] = rsqrtf(var + EPSV);
        }
        __syncthreads();
        float mu = fbc[0], inv = fbc[1];
        float d = ((v[0] - mu) * inv * out_g[t]       + out_b[t])       * head_w[t]
                + ((v[1] - mu) * inv * out_g[t + 256] + out_b[t + 256]) * head_w[t + 256]
                + ((v[2] - mu) * inv * out_g[t + 512] + out_b[t + 512]) * head_w[t + 512];
        for (int off = 16; off > 0; off >>= 1) d += __shfl_down_sync(0xffffffffu, d, off);
        __syncthreads();
        if (lane == 0) fr1[wid] = d;
        __syncthreads();
        if (t == 0) {
            float dd = 0.f;
            for (int w = 0; w < 8; w++) dd += fr1[w];
            out[row] = dd + head_b[0];
        }
    }
}

// ---------------- launch ----------------
extern "C" void kernel_launch(void* const* d_in, const int* in_sizes, int n_in,
                              void* d_out, int out_size) {
    const float* x        = (const float*)d_in[0];
    const float* w_in     = (const float*)d_in[1];
    const float* b_in     = (const float*)d_in[2];
    const float* ln_g     = (const float*)d_in[3];
    const float* ln_b     = (const float*)d_in[4];
    const float* trop_w   = (const float*)d_in[5];
    const float* trop_b   = (const float*)d_in[6];
    const float* lf_amax  = (const float*)d_in[7];
    const float* lf_bmax  = (const float*)d_in[8];
    const float* lf_amin  = (const float*)d_in[9];
    const float* lf_bmin  = (const float*)d_in[10];
    const float* lf_alpha = (const float*)d_in[11];
    const float* gate_w   = (const float*)d_in[12];
    const float* gate_b   = (const float*)d_in[13];
    const float* cls_w    = (const float*)d_in[14];
    const float* cls_b    = (const float*)d_in[15];
    const float* out_g    = (const float*)d_in[16];
    const float* out_b    = (const float*)d_in[17];
    const float* head_w   = (const float*)d_in[18];
    const float* head_b   = (const float*)d_in[19];
    float* out = (float*)d_out;

    cudaFuncSetAttribute(k_gemm_mma, cudaFuncAttributeMaxDynamicSharedMemorySize, SMEM_GEMM);

    k_prep<<<dim3(NH / 32, NH / 32, NL + 2 * NL), dim3(32, 8)>>>(trop_w, cls_w, gate_w);
    k_input<<<dim3(6, 32), 256>>>(x, w_in, b_in);
    k_ln0<<<NB, 256>>>(ln_g, ln_b);
    for (int l = 0; l < NL; l++) {
        k_gemm_mma<<<dim3(12, 4, 6), 256, SMEM_GEMM>>>(l);
        k_epi<<<NB, 256>>>(l, cls_b, gate_b, trop_b,
                           lf_amax, lf_bmax, lf_amin, lf_bmin, lf_alpha,
                           ln_g, ln_b, out_g, out_b, head_w, head_b, out);
    }
}

// round 10
// speedup vs baseline: 1.7578x; 1.0177x over previous
#include <cuda_runtime.h>
#include <cuda_bf16.h>
#include <cstdint>
#include <math.h>

// ---------------- problem constants ----------------
constexpr int NB  = 256;
constexpr int NIN = 64;
constexpr int NH  = 768;
constexpr int NL  = 4;
constexpr int NP  = 8;
#define EPSV 1e-5f

typedef unsigned long long u64;
typedef uint32_t u32;

// ---------------- device scratch ----------------
__device__ float          g_h[NB * NH];                 // residual stream
__device__ __nv_bfloat16  g_ahi[NB * NH];               // hn hi (bf16)
__device__ __nv_bfloat16  g_alo[NB * NH];               // hn lo (bf16)
__device__ float          g_tropT[NL * NH * NH];        // [l][i][o]
__device__ __nv_bfloat16  g_wT_hi[2 * NL * NH * NH];    // [mat*NL+l][o][i]
__device__ __nv_bfloat16  g_wT_lo[2 * NL * NH * NH];
__device__ float          g_part[12 * NB * NH];         // [(kp*2+mat)][row][o], kp in 0..5
// replay-idempotent: atomic max/min over identical inputs -> identical values each run
__device__ unsigned       g_wmax_enc[NL] = {0u, 0u, 0u, 0u};
__device__ unsigned       g_wmin_enc[NL] = {0xFFFFFFFFu, 0xFFFFFFFFu, 0xFFFFFFFFu, 0xFFFFFFFFu};
__device__ float          g_cand_val[NB * NH];
__device__ int            g_cand_idx[NB * NH];
__device__ int            g_cand_cnt[NB];

// order-preserving float <-> uint
__device__ __forceinline__ unsigned f2ord(float f) {
    unsigned u = __float_as_uint(f);
    return (u & 0x80000000u) ? ~u : (u | 0x80000000u);
}
__device__ __forceinline__ float ord2f(unsigned u) {
    return __uint_as_float((u & 0x80000000u) ? (u ^ 0x80000000u) : ~u);
}
__device__ __forceinline__ float sigmoidf_(float x) { return 1.0f / (1.0f + __expf(-x)); }

__device__ __forceinline__ u32 smem_u32(const void* p) {
    u32 a;
    asm("{ .reg .u64 t; cvta.to.shared.u64 t, %1; cvt.u32.u64 %0, t; }" : "=r"(a) : "l"(p));
    return a;
}
__device__ __forceinline__ void ldsm4(u32& r0, u32& r1, u32& r2, u32& r3, u32 a) {
    asm volatile("ldmatrix.sync.aligned.m8n8.x4.shared.b16 {%0,%1,%2,%3}, [%4];"
                 : "=r"(r0), "=r"(r1), "=r"(r2), "=r"(r3) : "r"(a));
}
__device__ __forceinline__ void mma16816(float* c, u32 a0, u32 a1, u32 a2, u32 a3, u32 b0, u32 b1) {
    asm volatile("mma.sync.aligned.m16n8k16.row.col.f32.bf16.bf16.f32 "
                 "{%0,%1,%2,%3}, {%4,%5,%6,%7}, {%8,%9}, {%0,%1,%2,%3};"
                 : "+f"(c[0]), "+f"(c[1]), "+f"(c[2]), "+f"(c[3])
                 : "r"(a0), "r"(a1), "r"(a2), "r"(a3), "r"(b0), "r"(b1));
}
__device__ __forceinline__ void cpa16(u32 dst, const void* src) {
    asm volatile("cp.async.cg.shared.global [%0], [%1], 16;" :: "r"(dst), "l"(src));
}
#define CPA_COMMIT() asm volatile("cp.async.commit_group;" ::: "memory")
#define CPA_WAIT(n)  asm volatile("cp.async.wait_group %0;" :: "n"(n) : "memory")

// ---------------- kernel 1: prep (trop transpose+minmax  |  weight transpose+bf16 hi/lo) ----------------
__global__ void k_prep(const float* __restrict__ tw,
                       const float* __restrict__ cls_w, const float* __restrict__ gate_w) {
    __shared__ float tile[32][33];
    int z  = blockIdx.z;
    int i0 = blockIdx.x * 32, o0 = blockIdx.y * 32;
    if (z < NL) {
        int l = z;
        const float* src = tw + (size_t)l * NH * NH;     // [o][i]
        float*       dst = g_tropT + (size_t)l * NH * NH;
        float lmax = -1e30f, lmin = 1e30f;
#pragma unroll
        for (int k = 0; k < 32; k += 8) {
            float v = src[(size_t)(o0 + threadIdx.y + k) * NH + (i0 + threadIdx.x)];
            tile[threadIdx.y + k][threadIdx.x] = v;
            lmax = fmaxf(lmax, v); lmin = fminf(lmin, v);
        }
        __syncthreads();
#pragma unroll
        for (int k = 0; k < 32; k += 8)
            dst[(size_t)(i0 + threadIdx.y + k) * NH + (o0 + threadIdx.x)] = tile[threadIdx.x][threadIdx.y + k];

        for (int off = 16; off > 0; off >>= 1) {
            lmax = fmaxf(lmax, __shfl_down_sync(0xffffffffu, lmax, off));
            lmin = fminf(lmin, __shfl_down_sync(0xffffffffu, lmin, off));
        }
        __shared__ float smax[8], smin[8];
        if (threadIdx.x == 0) { smax[threadIdx.y] = lmax; smin[threadIdx.y] = lmin; }
        __syncthreads();
        if (threadIdx.y == 0 && threadIdx.x == 0) {
            float bm = smax[0], bn = smin[0];
            for (int w = 1; w < 8; w++) { bm = fmaxf(bm, smax[w]); bn = fminf(bn, smin[w]); }
            atomicMax(&g_wmax_enc[l], f2ord(bm));
            atomicMin(&g_wmin_enc[l], f2ord(bn));
        }
    } else {
        int zz = z - NL;                  // zz = mat*NL + l
        int mat = zz >> 2, l = zz & 3;
        const float* src = (mat ? gate_w : cls_w) + (size_t)l * NH * NH;   // [i][o]
#pragma unroll
        for (int k = 0; k < 32; k += 8)
            tile[threadIdx.y + k][threadIdx.x] = src[(size_t)(i0 + threadIdx.y + k) * NH + (o0 + threadIdx.x)];
        __syncthreads();
#pragma unroll
        for (int k = 0; k < 32; k += 8) {
            float v = tile[threadIdx.x][threadIdx.y + k];
            __nv_bfloat16 hi = __float2bfloat16(v);
            __nv_bfloat16 lo = __float2bfloat16(v - __bfloat162float(hi));
            size_t idx = ((size_t)zz * NH + (o0 + threadIdx.y + k)) * NH + (i0 + threadIdx.x);
            g_wT_hi[idx] = hi;
            g_wT_lo[idx] = lo;
        }
    }
}

// ---------------- shared block routine: LayerNorm + candidate extraction ----------------
__device__ __forceinline__ void ln_and_candidates(
    int row, int t, float v0, float v1, float v2,
    const float* __restrict__ ln_g, const float* __restrict__ ln_b, int lc)
{
    __shared__ float r1[8], r2[8], bc[2];
    __shared__ int cnt;
    int lane = t & 31, wid = t >> 5;
    float s = v0 + v1 + v2;
    float q = v0 * v0 + v1 * v1 + v2 * v2;
    for (int off = 16; off > 0; off >>= 1) {
        s += __shfl_down_sync(0xffffffffu, s, off);
        q += __shfl_down_sync(0xffffffffu, q, off);
    }
    if (lane == 0) { r1[wid] = s; r2[wid] = q; }
    __syncthreads();
    if (t == 0) {
        float ss = 0.f, qq = 0.f;
        for (int w = 0; w < 8; w++) { ss += r1[w]; qq += r2[w]; }
        float mu  = ss / (float)NH;
        float var = fmaxf(qq / (float)NH - mu * mu, 0.f);
        bc[0] = mu; bc[1] = rsqrtf(var + EPSV);
        cnt = 0;
    }
    __syncthreads();
    float mu = bc[0], inv = bc[1];
    const float* G  = ln_g + lc * NH;
    const float* Bv = ln_b + lc * NH;
    float h0 = (v0 - mu) * inv * G[t]       + Bv[t];
    float h1 = (v1 - mu) * inv * G[t + 256] + Bv[t + 256];
    float h2 = (v2 - mu) * inv * G[t + 512] + Bv[t + 512];
#pragma unroll
    for (int k = 0; k < 3; k++) {
        int j = t + k * 256;
        float hv = (k == 0 ? h0 : (k == 1 ? h1 : h2));
        __nv_bfloat16 hi = __float2bfloat16(hv);
        g_ahi[row * NH + j] = hi;
        g_alo[row * NH + j] = __float2bfloat16(hv - __bfloat162float(hi));
    }
    float m = fmaxf(h0, fmaxf(h1, h2));
    for (int off = 16; off > 0; off >>= 1) m = fmaxf(m, __shfl_down_sync(0xffffffffu, m, off));
    if (lane == 0) r1[wid] = m;
    __syncthreads();
    if (t == 0) {
        float mm = r1[0];
        for (int w = 1; w < 8; w++) mm = fmaxf(mm, r1[w]);
        bc[0] = mm;
    }
    __syncthreads();
    // EXACT pruning: i can win max_i(hn[i]+W[o,i]) only if hn[i] >= rowmax - (Wmax-Wmin)
    float spread = ord2f(g_wmax_enc[lc]) - ord2f(g_wmin_enc[lc]);
    float tau = bc[0] - spread - 1e-6f;
    if (h0 >= tau) { int p = atomicAdd(&cnt, 1); g_cand_val[row * NH + p] = h0; g_cand_idx[row * NH + p] = t; }
    if (h1 >= tau) { int p = atomicAdd(&cnt, 1); g_cand_val[row * NH + p] = h1; g_cand_idx[row * NH + p] = t + 256; }
    if (h2 >= tau) { int p = atomicAdd(&cnt, 1); g_cand_val[row * NH + p] = h2; g_cand_idx[row * NH + p] = t + 512; }
    __syncthreads();
    if (t == 0) g_cand_cnt[row] = cnt;
}

// ---------------- kernel 2: input GEMM, smem-tiled ----------------
__global__ void __launch_bounds__(256) k_input(
    const float* __restrict__ x, const float* __restrict__ w_in, const float* __restrict__ b_in)
{
    __shared__ float ws[NIN * 128];    // 32 KB
    __shared__ float xs[8 * NIN];      // 2 KB
    int jc = blockIdx.x * 128, r0 = blockIdx.y * 8;
    int t = threadIdx.x;
#pragma unroll
    for (int i = 0; i < 32; i++) {
        int idx = t + i * 256;
        int ik = idx >> 7, j = idx & 127;
        ws[idx] = w_in[ik * NH + jc + j];
    }
#pragma unroll
    for (int i = 0; i < 2; i++) {
        int idx = t + i * 256;
        int r = idx >> 6, ik = idx & 63;
        xs[idx] = x[(r0 + r) * NIN + ik];
    }
    __syncthreads();

    int j = t & 127, rh = t >> 7;
    float acc0, acc1, acc2, acc3;
    acc0 = acc1 = acc2 = acc3 = b_in[jc + j];
    const float* xr = xs + rh * 4 * NIN;
#pragma unroll 8
    for (int i = 0; i < NIN; i++) {
        float w = ws[i * 128 + j];
        acc0 += xr[i] * w;
        acc1 += xr[NIN + i] * w;
        acc2 += xr[2 * NIN + i] * w;
        acc3 += xr[3 * NIN + i] * w;
    }
    int rb = r0 + rh * 4;
    g_h[(rb + 0) * NH + jc + j] = acc0;
    g_h[(rb + 1) * NH + jc + j] = acc1;
    g_h[(rb + 2) * NH + jc + j] = acc2;
    g_h[(rb + 3) * NH + jc + j] = acc3;
}

// ---------------- kernel 3: LN + candidates for layer 0 ----------------
__global__ void k_ln0(const float* __restrict__ ln_g, const float* __restrict__ ln_b) {
    int row = blockIdx.x, t = threadIdx.x;
    float v0 = g_h[row * NH + t];
    float v1 = g_h[row * NH + t + 256];
    float v2 = g_h[row * NH + t + 512];
    ln_and_candidates(row, t, v0, v1, v2, ln_g, ln_b, 0);
}

// ---------------- kernel 4: dual GEMM, mma.sync bf16 hi/lo, cp.async 3-stage, K-split x6 ----------------
// grid (12, 4, 6): x = n-tile (128 over 2*768), y = m-tile (64), z = kp.
// kp: pass = kp>>1 (0 hh, 1 hl, 2 lh), k-half = kp&1 (6 chunks of 64 each).
// 288 CTAs of 256 threads -> 2 CTAs/SM. Warp tile 32m x 32n (mw = w&1, nw = w>>1):
// per chunk/warp 16 ldsm.x4 + 32 mma (was 20+32); ks-level fragment double-buffering.
constexpr int LDS_PAD = 72;                        // bf16/row (144 B) — conflict-free ldmatrix
constexpr int A_ELE = 64 * LDS_PAD;                // 4608
constexpr int B_ELE = 128 * LDS_PAD;               // 9216
constexpr int BUF_BYTES = (A_ELE + B_ELE) * 2;     // 27648
constexpr int STAGES = 3;
constexpr int SMEM_GEMM = STAGES * BUF_BYTES;      // 82944 -> 2 CTAs/SM fit in 228KB

__global__ void __launch_bounds__(256, 2) k_gemm_mma(int l) {
    extern __shared__ __nv_bfloat16 sm[];
    u32 sbase = smem_u32(sm);
    int t = threadIdx.x, lane = t & 31, w = t >> 5;
    int mw = w & 1, nw = w >> 1;          // 2 warps over m (32 each), 4 over n (32 each)
    int nb = blockIdx.x;
    int m0 = blockIdx.y * 64;
    int kp = blockIdx.z;
    int pass = kp >> 1;                   // 0: Ahi*Bhi, 1: Ahi*Blo, 2: Alo*Bhi
    int kh = kp & 1;                      // k half
    int mat = nb / 6;
    int o0 = (nb % 6) * 128;

    const __nv_bfloat16* As = (pass < 2 ? g_ahi : g_alo) + (size_t)m0 * NH;
    const __nv_bfloat16* Bs = (pass == 1 ? g_wT_lo : g_wT_hi) + ((size_t)(mat * NL + l) * NH + o0) * NH;

    float acc[2][4][4];                   // [m-frag][n-oct][4]
#pragma unroll
    for (int f = 0; f < 2; f++)
#pragma unroll
        for (int i = 0; i < 4; i++)
#pragma unroll
            for (int j = 0; j < 4; j++) acc[f][i][j] = 0.f;

    // per-thread cp.async source/dest decomposition (256 thr = 32 rows x 8 16B-cols)
    int ur = t >> 3, uc = t & 7;
    int cbase = kh * 6;                   // 6 chunks of 64 in this CTA's k-half

#define ISSUE_CHUNK(c, s)                                                           \
    {                                                                               \
        int kc = (c) * 64;                                                          \
        u32 abase = sbase + (s) * BUF_BYTES;                                        \
        u32 bbase = abase + A_ELE * 2;                                              \
        _Pragma("unroll")                                                           \
        for (int i = 0; i < 2; i++) {                                               \
            int r = ur + i * 32;                                                    \
            cpa16(abase + (u32)(r * LDS_PAD + uc * 8) * 2,                          \
                  As + (size_t)r * NH + kc + uc * 8);                               \
        }                                                                           \
        _Pragma("unroll")                                                           \
        for (int i = 0; i < 4; i++) {                                               \
            int r = ur + i * 32;                                                    \
            cpa16(bbase + (u32)(r * LDS_PAD + uc * 8) * 2,                          \
                  Bs + (size_t)r * NH + kc + uc * 8);                               \
        }                                                                           \
        CPA_COMMIT();                                                               \
    }

    // ldmatrix per-thread offsets
    int ar = (lane & 7) + ((lane >> 3) & 1) * 8;     // row within 16
    int ac = (lane >> 4) * 8;                        // k offset 0/8
    u32 a_off0 = (u32)((mw * 32 + ar) * LDS_PAD + ac) * 2;          // m-frag 0
    u32 a_off1 = (u32)((mw * 32 + 16 + ar) * LDS_PAD + ac) * 2;     // m-frag 1
    int bn = (lane & 7) + ((lane >> 4) & 1) * 8;
    int bk = ((lane >> 3) & 1) * 8;
    u32 b_off0 = (u32)((nw * 32 + bn) * LDS_PAD + bk) * 2;          // n 0..15
    u32 b_off1 = (u32)((nw * 32 + 16 + bn) * LDS_PAD + bk) * 2;     // n 16..31

    ISSUE_CHUNK(cbase + 0, 0);
    ISSUE_CHUNK(cbase + 1, 1);

    u32 af[2][8], bf[2][8];               // double-buffered fragments over ks

    for (int ci = 0; ci < 6; ci++) {
        if (ci < 5) { CPA_WAIT(1); } else { CPA_WAIT(0); }
        __syncthreads();
        int s = ci % 3;
        u32 ab = sbase + (u32)s * BUF_BYTES;
        u32 bb = ab + A_ELE * 2;

        // prefetch ks = 0 fragments
        ldsm4(af[0][0], af[0][1], af[0][2], af[0][3], ab + a_off0);
        ldsm4(af[0][4], af[0][5], af[0][6], af[0][7], ab + a_off1);
        ldsm4(bf[0][0], bf[0][1], bf[0][2], bf[0][3], bb + b_off0);
        ldsm4(bf[0][4], bf[0][5], bf[0][6], bf[0][7], bb + b_off1);

#pragma unroll
        for (int ks = 0; ks < 4; ks++) {
            int cur = ks & 1, nxt = cur ^ 1;
            if (ks < 3) {
                u32 ko = (u32)(ks + 1) * 32;
                ldsm4(af[nxt][0], af[nxt][1], af[nxt][2], af[nxt][3], ab + a_off0 + ko);
                ldsm4(af[nxt][4], af[nxt][5], af[nxt][6], af[nxt][7], ab + a_off1 + ko);
                ldsm4(bf[nxt][0], bf[nxt][1], bf[nxt][2], bf[nxt][3], bb + b_off0 + ko);
                ldsm4(bf[nxt][4], bf[nxt][5], bf[nxt][6], bf[nxt][7], bb + b_off1 + ko);
            }
#pragma unroll
            for (int f = 0; f < 2; f++) {
                u32* a = af[cur] + f * 4;
#pragma unroll
                for (int nt = 0; nt < 2; nt++) {
                    u32* b = bf[cur] + nt * 4;
                    mma16816(acc[f][nt * 2],     a[0], a[1], a[2], a[3], b[0], b[1]);
                    mma16816(acc[f][nt * 2 + 1], a[0], a[1], a[2], a[3], b[2], b[3]);
                }
            }
        }
        if (ci + 2 < 6) ISSUE_CHUNK(cbase + ci + 2, (ci + 2) % 3);
    }
#undef ISSUE_CHUNK

    // store partials: C frag rows mw*32 + f*16 + r (+8), cols nw*32 + nt*16 + pair*8 + c2
    int r = lane >> 2, c2 = (lane & 3) * 2;
#pragma unroll
    for (int f = 0; f < 2; f++)
#pragma unroll
        for (int nt = 0; nt < 2; nt++)
#pragma unroll
            for (int pair = 0; pair < 2; pair++) {
                int o = o0 + nw * 32 + nt * 16 + pair * 8 + c2;
                int rowb = m0 + mw * 32 + f * 16 + r;
                float* acc4 = acc[f][nt * 2 + pair];
                float* dst = g_part + ((size_t)(kp * 2 + mat) * NB + rowb) * NH + o;
                *(float2*)dst = make_float2(acc4[0], acc4[1]);
                *(float2*)(dst + (size_t)8 * NH) = make_float2(acc4[2], acc4[3]);
            }
}

// ---------------- kernel 5: epilogue + next LN / final head ----------------
__global__ void k_epi(int l,
    const float* __restrict__ cls_b,  const float* __restrict__ gate_b,
    const float* __restrict__ trop_b,
    const float* __restrict__ lf_amax, const float* __restrict__ lf_bmax,
    const float* __restrict__ lf_amin, const float* __restrict__ lf_bmin,
    const float* __restrict__ lf_alpha,
    const float* __restrict__ ln_g,   const float* __restrict__ ln_b,
    const float* __restrict__ out_g,  const float* __restrict__ out_b,
    const float* __restrict__ head_w, const float* __restrict__ head_b,
    float* __restrict__ out)
{
    __shared__ float scv[64];
    __shared__ int   sci[64];
    int row = blockIdx.x, t = threadIdx.x;
    int cnt = g_cand_cnt[row];
    if (cnt > 64) cnt = 64;   // safety clamp (expected cnt ~ 2-6)
    for (int c = t; c < cnt; c += 256) {
        scv[c] = g_cand_val[row * NH + c];
        sci[c] = g_cand_idx[row * NH + c];
    }
    __syncthreads();

    const float* tT = g_tropT + (size_t)l * NH * NH;
    float v[3];
#pragma unroll
    for (int k = 0; k < 3; k++) {
        int j = t + k * 256;
        // fixed-order partial merge (deterministic): slots kp*2+mat, kp in 0..5
        float c = 0.f, g = 0.f;
#pragma unroll
        for (int kp = 0; kp < 6; kp++) {
            c += g_part[((size_t)(kp * 2 + 0) * NB + row) * NH + j];
            g += g_part[((size_t)(kp * 2 + 1) * NB + row) * NH + j];
        }
        c += cls_b[l * NH + j];
        g += gate_b[l * NH + j];

        float tm = -1e30f;
        for (int cc = 0; cc < cnt; cc++)
            tm = fmaxf(tm, scv[cc] + tT[(size_t)sci[cc] * NH + j]);
        float tt = tm + trop_b[l * NH + j];

        const float4* AM  = (const float4*)(lf_amax + ((size_t)l * NH + j) * NP);
        const float4* BM  = (const float4*)(lf_bmax + ((size_t)l * NH + j) * NP);
        const float4* AN  = (const float4*)(lf_amin + ((size_t)l * NH + j) * NP);
        const float4* BMN = (const float4*)(lf_bmin + ((size_t)l * NH + j) * NP);
        float fmx = -1e30f, fmn = 1e30f;
#pragma unroll
        for (int q = 0; q < 2; q++) {
            float4 am = AM[q], bm = BM[q], an = AN[q], bn = BMN[q];
            fmx = fmaxf(fmx, fmaxf(fmaxf(tt * am.x + bm.x, tt * am.y + bm.y),
                                   fmaxf(tt * am.z + bm.z, tt * am.w + bm.w)));
            fmn = fminf(fmn, fminf(fminf(tt * an.x + bn.x, tt * an.y + bn.y),
                                   fminf(tt * an.z + bn.z, tt * an.w + bn.w)));
        }
        float a_ = sigmoidf_(lf_alpha[l * NH + j]);
        float trop_out = a_ * fmx + (1.0f - a_) * fmn;
        float cls_out = 0.5f * c * (1.0f + erff(c * 0.70710678118654752f));
        float gg = sigmoidf_(g);
        v[k] = g_h[row * NH + j] + gg * trop_out + (1.0f - gg) * cls_out;
        g_h[row * NH + j] = v[k];
    }
    __syncthreads();

    if (l < NL - 1) {
        ln_and_candidates(row, t, v[0], v[1], v[2], ln_g, ln_b, l + 1);
    } else {
        __shared__ float fr1[8], fr2[8], fbc[2];
        int lane = t & 31, wid = t >> 5;
        float s = v[0] + v[1] + v[2];
        float q = v[0] * v[0] + v[1] * v[1] + v[2] * v[2];
        for (int off = 16; off > 0; off >>= 1) {
            s += __shfl_down_sync(0xffffffffu, s, off);
            q += __shfl_down_sync(0xffffffffu, q, off);
        }
        if (lane == 0) { fr1[wid] = s; fr2[wid] = q; }
        __syncthreads();
        if (t == 0) {
            float ss = 0.f, qq = 0.f;
            for (int w = 0; w < 8; w++) { ss += fr1[w]; qq += fr2[w]; }
            float mu  = ss / (float)NH;
            float var = fmaxf(qq / (float)NH - mu * mu, 0.f);
            fbc[0] = mu; fbc[1] = rsqrtf(var + EPSV);
        }
        __syncthreads();
        float mu = fbc[0], inv = fbc[1];
        float d = ((v[0] - mu) * inv * out_g[t]       + out_b[t])       * head_w[t]
                + ((v[1] - mu) * inv * out_g[t + 256] + out_b[t + 256]) * head_w[t + 256]
                + ((v[2] - mu) * inv * out_g[t + 512] + out_b[t + 512]) * head_w[t + 512];
        for (int off = 16; off > 0; off >>= 1) d += __shfl_down_sync(0xffffffffu, d, off);
        __syncthreads();
        if (lane == 0) fr1[wid] = d;
        __syncthreads();
        if (t == 0) {
            float dd = 0.f;
            for (int w = 0; w < 8; w++) dd += fr1[w];
            out[row] = dd + head_b[0];
        }
    }
}

// ---------------- launch ----------------
extern "C" void kernel_launch(void* const* d_in, const int* in_sizes, int n_in,
                              void* d_out, int out_size) {
    const float* x        = (const float*)d_in[0];
    const float* w_in     = (const float*)d_in[1];
    const float* b_in     = (const float*)d_in[2];
    const float* ln_g     = (const float*)d_in[3];
    const float* ln_b     = (const float*)d_in[4];
    const float* trop_w   = (const float*)d_in[5];
    const float* trop_b   = (const float*)d_in[6];
    const float* lf_amax  = (const float*)d_in[7];
    const float* lf_bmax  = (const float*)d_in[8];
    const float* lf_amin  = (const float*)d_in[9];
    const float* lf_bmin  = (const float*)d_in[10];
    const float* lf_alpha = (const float*)d_in[11];
    const float* gate_w   = (const float*)d_in[12];
    const float* gate_b   = (const float*)d_in[13];
    const float* cls_w    = (const float*)d_in[14];
    const float* cls_b    = (const float*)d_in[15];
    const float* out_g    = (const float*)d_in[16];
    const float* out_b    = (const float*)d_in[17];
    const float* head_w   = (const float*)d_in[18];
    const float* head_b   = (const float*)d_in[19];
    float* out = (float*)d_out;

    cudaFuncSetAttribute(k_gemm_mma, cudaFuncAttributeMaxDynamicSharedMemorySize, SMEM_GEMM);

    k_prep<<<dim3(NH / 32, NH / 32, NL + 2 * NL), dim3(32, 8)>>>(trop_w, cls_w, gate_w);
    k_input<<<dim3(6, 32), 256>>>(x, w_in, b_in);
    k_ln0<<<NB, 256>>>(ln_g, ln_b);
    for (int l = 0; l < NL; l++) {
        k_gemm_mma<<<dim3(12, 4, 6), 256, SMEM_GEMM>>>(l);
        k_epi<<<NB, 256>>>(l, cls_b, gate_b, trop_b,
                           lf_amax, lf_bmax, lf_amin, lf_bmin, lf_alpha,
                           ln_g, ln_b, out_g, out_b, head_w, head_b, out);
    }
}

// round 14
// speedup vs baseline: 1.8856x; 1.0727x over previous
#include <cuda_runtime.h>
#include <cuda_bf16.h>
#include <cstdint>
#include <math.h>

// ---------------- problem constants ----------------
constexpr int NB  = 256;
constexpr int NIN = 64;
constexpr int NH  = 768;
constexpr int NL  = 4;
constexpr int NP  = 8;
#define EPSV 1e-5f

typedef unsigned long long u64;
typedef uint32_t u32;

// ---------------- device scratch ----------------
__device__ float          g_h[NB * NH];                 // residual stream
__device__ __nv_bfloat16  g_ahi[NB * NH];               // hn hi (bf16)
__device__ __nv_bfloat16  g_alo[NB * NH];               // hn lo (bf16)
__device__ float          g_tropT[NL * NH * NH];        // [l][i][o]
__device__ __nv_bfloat16  g_wT_hi[2 * NL * NH * NH];    // [mat*NL+l][o][i]
__device__ __nv_bfloat16  g_wT_lo[2 * NL * NH * NH];
__device__ float          g_part[12 * NB * NH];         // [(kz*2+mat)][row][o], kz in 0..5
// replay-idempotent: atomic max/min over identical inputs -> identical values each run
__device__ unsigned       g_wmax_enc[NL] = {0u, 0u, 0u, 0u};
__device__ unsigned       g_wmin_enc[NL] = {0xFFFFFFFFu, 0xFFFFFFFFu, 0xFFFFFFFFu, 0xFFFFFFFFu};
__device__ float          g_cand_val[NB * NH];
__device__ int            g_cand_idx[NB * NH];
__device__ int            g_cand_cnt[NB];

// order-preserving float <-> uint
__device__ __forceinline__ unsigned f2ord(float f) {
    unsigned u = __float_as_uint(f);
    return (u & 0x80000000u) ? ~u : (u | 0x80000000u);
}
__device__ __forceinline__ float ord2f(unsigned u) {
    return __uint_as_float((u & 0x80000000u) ? (u ^ 0x80000000u) : ~u);
}
__device__ __forceinline__ float sigmoidf_(float x) { return 1.0f / (1.0f + __expf(-x)); }

__device__ __forceinline__ u32 smem_u32(const void* p) {
    u32 a;
    asm("{ .reg .u64 t; cvta.to.shared.u64 t, %1; cvt.u32.u64 %0, t; }" : "=r"(a) : "l"(p));
    return a;
}
__device__ __forceinline__ void ldsm4(u32& r0, u32& r1, u32& r2, u32& r3, u32 a) {
    asm volatile("ldmatrix.sync.aligned.m8n8.x4.shared.b16 {%0,%1,%2,%3}, [%4];"
                 : "=r"(r0), "=r"(r1), "=r"(r2), "=r"(r3) : "r"(a));
}
__device__ __forceinline__ void mma16816(float* c, u32 a0, u32 a1, u32 a2, u32 a3, u32 b0, u32 b1) {
    asm volatile("mma.sync.aligned.m16n8k16.row.col.f32.bf16.bf16.f32 "
                 "{%0,%1,%2,%3}, {%4,%5,%6,%7}, {%8,%9}, {%0,%1,%2,%3};"
                 : "+f"(c[0]), "+f"(c[1]), "+f"(c[2]), "+f"(c[3])
                 : "r"(a0), "r"(a1), "r"(a2), "r"(a3), "r"(b0), "r"(b1));
}
__device__ __forceinline__ void cpa16(u32 dst, const void* src) {
    asm volatile("cp.async.cg.shared.global [%0], [%1], 16;" :: "r"(dst), "l"(src));
}
#define CPA_COMMIT() asm volatile("cp.async.commit_group;" ::: "memory")
#define CPA_WAIT(n)  asm volatile("cp.async.wait_group %0;" :: "n"(n) : "memory")

// ---------------- kernel 1: prep (trop transpose+minmax  |  weight transpose+bf16 hi/lo) ----------------
__global__ void k_prep(const float* __restrict__ tw,
                       const float* __restrict__ cls_w, const float* __restrict__ gate_w) {
    __shared__ float tile[32][33];
    int z  = blockIdx.z;
    int i0 = blockIdx.x * 32, o0 = blockIdx.y * 32;
    if (z < NL) {
        int l = z;
        const float* src = tw + (size_t)l * NH * NH;     // [o][i]
        float*       dst = g_tropT + (size_t)l * NH * NH;
        float lmax = -1e30f, lmin = 1e30f;
#pragma unroll
        for (int k = 0; k < 32; k += 8) {
            float v = src[(size_t)(o0 + threadIdx.y + k) * NH + (i0 + threadIdx.x)];
            tile[threadIdx.y + k][threadIdx.x] = v;
            lmax = fmaxf(lmax, v); lmin = fminf(lmin, v);
        }
        __syncthreads();
#pragma unroll
        for (int k = 0; k < 32; k += 8)
            dst[(size_t)(i0 + threadIdx.y + k) * NH + (o0 + threadIdx.x)] = tile[threadIdx.x][threadIdx.y + k];

        for (int off = 16; off > 0; off >>= 1) {
            lmax = fmaxf(lmax, __shfl_down_sync(0xffffffffu, lmax, off));
            lmin = fminf(lmin, __shfl_down_sync(0xffffffffu, lmin, off));
        }
        __shared__ float smax[8], smin[8];
        if (threadIdx.x == 0) { smax[threadIdx.y] = lmax; smin[threadIdx.y] = lmin; }
        __syncthreads();
        if (threadIdx.y == 0 && threadIdx.x == 0) {
            float bm = smax[0], bn = smin[0];
            for (int w = 1; w < 8; w++) { bm = fmaxf(bm, smax[w]); bn = fminf(bn, smin[w]); }
            atomicMax(&g_wmax_enc[l], f2ord(bm));
            atomicMin(&g_wmin_enc[l], f2ord(bn));
        }
    } else {
        int zz = z - NL;                  // zz = mat*NL + l
        int mat = zz >> 2, l = zz & 3;
        const float* src = (mat ? gate_w : cls_w) + (size_t)l * NH * NH;   // [i][o]
#pragma unroll
        for (int k = 0; k < 32; k += 8)
            tile[threadIdx.y + k][threadIdx.x] = src[(size_t)(i0 + threadIdx.y + k) * NH + (o0 + threadIdx.x)];
        __syncthreads();
#pragma unroll
        for (int k = 0; k < 32; k += 8) {
            float v = tile[threadIdx.x][threadIdx.y + k];
            __nv_bfloat16 hi = __float2bfloat16(v);
            __nv_bfloat16 lo = __float2bfloat16(v - __bfloat162float(hi));
            size_t idx = ((size_t)zz * NH + (o0 + threadIdx.y + k)) * NH + (i0 + threadIdx.x);
            g_wT_hi[idx] = hi;
            g_wT_lo[idx] = lo;
        }
    }
}

// ---------------- shared block routine: LayerNorm + candidate extraction ----------------
__device__ __forceinline__ void ln_and_candidates(
    int row, int t, float v0, float v1, float v2,
    const float* __restrict__ ln_g, const float* __restrict__ ln_b, int lc)
{
    __shared__ float r1[8], r2[8], bc[2];
    __shared__ int cnt;
    int lane = t & 31, wid = t >> 5;
    float s = v0 + v1 + v2;
    float q = v0 * v0 + v1 * v1 + v2 * v2;
    for (int off = 16; off > 0; off >>= 1) {
        s += __shfl_down_sync(0xffffffffu, s, off);
        q += __shfl_down_sync(0xffffffffu, q, off);
    }
    if (lane == 0) { r1[wid] = s; r2[wid] = q; }
    __syncthreads();
    if (t == 0) {
        float ss = 0.f, qq = 0.f;
        for (int w = 0; w < 8; w++) { ss += r1[w]; qq += r2[w]; }
        float mu  = ss / (float)NH;
        float var = fmaxf(qq / (float)NH - mu * mu, 0.f);
        bc[0] = mu; bc[1] = rsqrtf(var + EPSV);
        cnt = 0;
    }
    __syncthreads();
    float mu = bc[0], inv = bc[1];
    const float* G  = ln_g + lc * NH;
    const float* Bv = ln_b + lc * NH;
    float h0 = (v0 - mu) * inv * G[t]       + Bv[t];
    float h1 = (v1 - mu) * inv * G[t + 256] + Bv[t + 256];
    float h2 = (v2 - mu) * inv * G[t + 512] + Bv[t + 512];
#pragma unroll
    for (int k = 0; k < 3; k++) {
        int j = t + k * 256;
        float hv = (k == 0 ? h0 : (k == 1 ? h1 : h2));
        __nv_bfloat16 hi = __float2bfloat16(hv);
        g_ahi[row * NH + j] = hi;
        g_alo[row * NH + j] = __float2bfloat16(hv - __bfloat162float(hi));
    }
    float m = fmaxf(h0, fmaxf(h1, h2));
    for (int off = 16; off > 0; off >>= 1) m = fmaxf(m, __shfl_down_sync(0xffffffffu, m, off));
    if (lane == 0) r1[wid] = m;
    __syncthreads();
    if (t == 0) {
        float mm = r1[0];
        for (int w = 1; w < 8; w++) mm = fmaxf(mm, r1[w]);
        bc[0] = mm;
    }
    __syncthreads();
    // EXACT pruning: i can win max_i(hn[i]+W[o,i]) only if hn[i] >= rowmax - (Wmax-Wmin)
    float spread = ord2f(g_wmax_enc[lc]) - ord2f(g_wmin_enc[lc]);
    float tau = bc[0] - spread - 1e-6f;
    if (h0 >= tau) { int p = atomicAdd(&cnt, 1); g_cand_val[row * NH + p] = h0; g_cand_idx[row * NH + p] = t; }
    if (h1 >= tau) { int p = atomicAdd(&cnt, 1); g_cand_val[row * NH + p] = h1; g_cand_idx[row * NH + p] = t + 256; }
    if (h2 >= tau) { int p = atomicAdd(&cnt, 1); g_cand_val[row * NH + p] = h2; g_cand_idx[row * NH + p] = t + 512; }
    __syncthreads();
    if (t == 0) g_cand_cnt[row] = cnt;
}

// ---------------- kernel 2: input GEMM, smem-tiled ----------------
__global__ void __launch_bounds__(256) k_input(
    const float* __restrict__ x, const float* __restrict__ w_in, const float* __restrict__ b_in)
{
    __shared__ float ws[NIN * 128];    // 32 KB
    __shared__ float xs[8 * NIN];      // 2 KB
    int jc = blockIdx.x * 128, r0 = blockIdx.y * 8;
    int t = threadIdx.x;
#pragma unroll
    for (int i = 0; i < 32; i++) {
        int idx = t + i * 256;
        int ik = idx >> 7, j = idx & 127;
        ws[idx] = w_in[ik * NH + jc + j];
    }
#pragma unroll
    for (int i = 0; i < 2; i++) {
        int idx = t + i * 256;
        int r = idx >> 6, ik = idx & 63;
        xs[idx] = x[(r0 + r) * NIN + ik];
    }
    __syncthreads();

    int j = t & 127, rh = t >> 7;
    float acc0, acc1, acc2, acc3;
    acc0 = acc1 = acc2 = acc3 = b_in[jc + j];
    const float* xr = xs + rh * 4 * NIN;
#pragma unroll 8
    for (int i = 0; i < NIN; i++) {
        float w = ws[i * 128 + j];
        acc0 += xr[i] * w;
        acc1 += xr[NIN + i] * w;
        acc2 += xr[2 * NIN + i] * w;
        acc3 += xr[3 * NIN + i] * w;
    }
    int rb = r0 + rh * 4;
    g_h[(rb + 0) * NH + jc + j] = acc0;
    g_h[(rb + 1) * NH + jc + j] = acc1;
    g_h[(rb + 2) * NH + jc + j] = acc2;
    g_h[(rb + 3) * NH + jc + j] = acc3;
}

// ---------------- kernel 3: LN + candidates for layer 0 ----------------
__global__ void k_ln0(const float* __restrict__ ln_g, const float* __restrict__ ln_b) {
    int row = blockIdx.x, t = threadIdx.x;
    float v0 = g_h[row * NH + t];
    float v1 = g_h[row * NH + t + 256];
    float v2 = g_h[row * NH + t + 512];
    ln_and_candidates(row, t, v0, v1, v2, ln_g, ln_b, 0);
}

// ---------------- kernel 4: dual GEMM, MERGED hi/lo passes (hh+hl+lh in one CTA) ----------------
// grid (12, 4, 6): x = n-tile (128 over 2*768), y = m-tile (64), z = kz (K sixth, 2 chunks of 64).
// 288 CTAs of 256 threads, 110.6 KB smem -> 2 CTAs/SM. Warp tile 32m x 32n.
// Per ks: 8 ldsm.x4 (Ahi,Alo,Bhi,Blo frags) -> 24 mma (hh, hl, lh into SAME acc). ratio 3.0.
// 2 chunks = 2 stages, both issued up-front: no steady-state re-issue, 1 wait+sync per chunk.
constexpr int LDS_PAD = 72;                        // bf16/row (144 B) — conflict-free ldmatrix
constexpr int A_T = 64 * LDS_PAD;                  // 4608 elems per A tile
constexpr int B_T = 128 * LDS_PAD;                 // 9216 elems per B tile
constexpr int OFF_AHI = 0;
constexpr int OFF_ALO = A_T * 2;                   // 9216 B
constexpr int OFF_BHI = 2 * A_T * 2;               // 18432 B
constexpr int OFF_BLO = (2 * A_T + B_T) * 2;       // 36864 B
constexpr int STG_BYTES = (2 * A_T + 2 * B_T) * 2; // 55296
constexpr int SMEM_GEMM = 2 * STG_BYTES;           // 110592 -> 2 CTAs/SM

__global__ void __launch_bounds__(256, 2) k_gemm_mma(int l) {
    extern __shared__ __nv_bfloat16 sm[];
    u32 sbase = smem_u32(sm);
    int t = threadIdx.x, lane = t & 31, w = t >> 5;
    int mw = w & 1, nw = w >> 1;          // 2 warps over m (32 each), 4 over n (32 each)
    int nb = blockIdx.x;
    int m0 = blockIdx.y * 64;
    int kz = blockIdx.z;                  // K sixth
    int mat = nb / 6;
    int o0 = (nb % 6) * 128;

    const __nv_bfloat16* Ah = g_ahi + (size_t)m0 * NH;
    const __nv_bfloat16* Al = g_alo + (size_t)m0 * NH;
    const __nv_bfloat16* Bh = g_wT_hi + ((size_t)(mat * NL + l) * NH + o0) * NH;
    const __nv_bfloat16* Bl = g_wT_lo + ((size_t)(mat * NL + l) * NH + o0) * NH;

    float acc[2][4][4];                   // [m-frag][n-oct][4]
#pragma unroll
    for (int f = 0; f < 2; f++)
#pragma unroll
        for (int i = 0; i < 4; i++)
#pragma unroll
            for (int j = 0; j < 4; j++) acc[f][i][j] = 0.f;

    // loader decomposition: 256 thr = 32 rows x 8 16B-cols
    int ur = t >> 3, uc = t & 7;

    // issue BOTH chunks up front (2 stages, 2 commit groups)
#pragma unroll
    for (int c = 0; c < 2; c++) {
        int kc = (kz * 2 + c) * 64;
        u32 st = sbase + (u32)c * STG_BYTES;
#pragma unroll
        for (int i = 0; i < 2; i++) {       // A tiles: 64 rows
            int r = ur + i * 32;
            u32 so = (u32)(r * LDS_PAD + uc * 8) * 2;
            cpa16(st + OFF_AHI + so, Ah + (size_t)r * NH + kc + uc * 8);
            cpa16(st + OFF_ALO + so, Al + (size_t)r * NH + kc + uc * 8);
        }
#pragma unroll
        for (int i = 0; i < 4; i++) {       // B tiles: 128 rows
            int r = ur + i * 32;
            u32 so = (u32)(r * LDS_PAD + uc * 8) * 2;
            cpa16(st + OFF_BHI + so, Bh + (size_t)r * NH + kc + uc * 8);
            cpa16(st + OFF_BLO + so, Bl + (size_t)r * NH + kc + uc * 8);
        }
        CPA_COMMIT();
    }

    // ldmatrix per-thread offsets
    int ar = (lane & 7) + ((lane >> 3) & 1) * 8;     // row within 16
    int ac = (lane >> 4) * 8;                        // k offset 0/8
    u32 a_off0 = (u32)((mw * 32 + ar) * LDS_PAD + ac) * 2;          // m-frag 0
    u32 a_off1 = (u32)((mw * 32 + 16 + ar) * LDS_PAD + ac) * 2;     // m-frag 1
    int bn = (lane & 7) + ((lane >> 4) & 1) * 8;
    int bk = ((lane >> 3) & 1) * 8;
    u32 b_off0 = (u32)((nw * 32 + bn) * LDS_PAD + bk) * 2;          // n 0..15
    u32 b_off1 = (u32)((nw * 32 + 16 + bn) * LDS_PAD + bk) * 2;     // n 16..31

#pragma unroll
    for (int c = 0; c < 2; c++) {
        if (c == 0) { CPA_WAIT(1); } else { CPA_WAIT(0); }
        __syncthreads();
        u32 st = sbase + (u32)c * STG_BYTES;
        u32 ahb = st + OFF_AHI, alb = st + OFF_ALO;
        u32 bhb = st + OFF_BHI, blb = st + OFF_BLO;
#pragma unroll
        for (int ks = 0; ks < 4; ks++) {
            u32 ko = (u32)ks * 32;
            u32 ah[8], al[8], bh[8], bl[8];
            ldsm4(ah[0], ah[1], ah[2], ah[3], ahb + a_off0 + ko);
            ldsm4(ah[4], ah[5], ah[6], ah[7], ahb + a_off1 + ko);
            ldsm4(al[0], al[1], al[2], al[3], alb + a_off0 + ko);
            ldsm4(al[4], al[5], al[6], al[7], alb + a_off1 + ko);
            ldsm4(bh[0], bh[1], bh[2], bh[3], bhb + b_off0 + ko);
            ldsm4(bh[4], bh[5], bh[6], bh[7], bhb + b_off1 + ko);
            ldsm4(bl[0], bl[1], bl[2], bl[3], blb + b_off0 + ko);
            ldsm4(bl[4], bl[5], bl[6], bl[7], blb + b_off1 + ko);
#pragma unroll
            for (int f = 0; f < 2; f++) {
                u32* xh = ah + f * 4;
                u32* xl = al + f * 4;
#pragma unroll
                for (int nt = 0; nt < 2; nt++) {
                    u32* yh = bh + nt * 4;
                    u32* yl = bl + nt * 4;
                    float* c0 = acc[f][nt * 2];
                    float* c1 = acc[f][nt * 2 + 1];
                    mma16816(c0, xh[0], xh[1], xh[2], xh[3], yh[0], yh[1]);  // hh
                    mma16816(c1, xh[0], xh[1], xh[2], xh[3], yh[2], yh[3]);
                    mma16816(c0, xh[0], xh[1], xh[2], xh[3], yl[0], yl[1]);  // hl
                    mma16816(c1, xh[0], xh[1], xh[2], xh[3], yl[2], yl[3]);
                    mma16816(c0, xl[0], xl[1], xl[2], xl[3], yh[0], yh[1]);  // lh
                    mma16816(c1, xl[0], xl[1], xl[2], xl[3], yh[2], yh[3]);
                }
            }
        }
    }

    // store partials: slot kz*2+mat; C frag rows mw*32 + f*16 + r (+8), cols nw*32 + nt*16 + pair*8 + c2
    int r = lane >> 2, c2 = (lane & 3) * 2;
#pragma unroll
    for (int f = 0; f < 2; f++)
#pragma unroll
        for (int nt = 0; nt < 2; nt++)
#pragma unroll
            for (int pair = 0; pair < 2; pair++) {
                int o = o0 + nw * 32 + nt * 16 + pair * 8 + c2;
                int rowb = m0 + mw * 32 + f * 16 + r;
                float* acc4 = acc[f][nt * 2 + pair];
                float* dst = g_part + ((size_t)(kz * 2 + mat) * NB + rowb) * NH + o;
                *(float2*)dst = make_float2(acc4[0], acc4[1]);
                *(float2*)(dst + (size_t)8 * NH) = make_float2(acc4[2], acc4[3]);
            }
}

// ---------------- kernel 5: epilogue + next LN / final head ----------------
__global__ void k_epi(int l,
    const float* __restrict__ cls_b,  const float* __restrict__ gate_b,
    const float* __restrict__ trop_b,
    const float* __restrict__ lf_amax, const float* __restrict__ lf_bmax,
    const float* __restrict__ lf_amin, const float* __restrict__ lf_bmin,
    const float* __restrict__ lf_alpha,
    const float* __restrict__ ln_g,   const float* __restrict__ ln_b,
    const float* __restrict__ out_g,  const float* __restrict__ out_b,
    const float* __restrict__ head_w, const float* __restrict__ head_b,
    float* __restrict__ out)
{
    __shared__ float scv[64];
    __shared__ int   sci[64];
    int row = blockIdx.x, t = threadIdx.x;
    int cnt = g_cand_cnt[row];
    if (cnt > 64) cnt = 64;   // safety clamp (expected cnt ~ 2-6)
    for (int c = t; c < cnt; c += 256) {
        scv[c] = g_cand_val[row * NH + c];
        sci[c] = g_cand_idx[row * NH + c];
    }
    __syncthreads();

    const float* tT = g_tropT + (size_t)l * NH * NH;
    float v[3];
#pragma unroll
    for (int k = 0; k < 3; k++) {
        int j = t + k * 256;
        // fixed-order partial merge (deterministic): slots kz*2+mat, kz in 0..5
        float c = 0.f, g = 0.f;
#pragma unroll
        for (int kp = 0; kp < 6; kp++) {
            c += g_part[((size_t)(kp * 2 + 0) * NB + row) * NH + j];
            g += g_part[((size_t)(kp * 2 + 1) * NB + row) * NH + j];
        }
        c += cls_b[l * NH + j];
        g += gate_b[l * NH + j];

        float tm = -1e30f;
        for (int cc = 0; cc < cnt; cc++)
            tm = fmaxf(tm, scv[cc] + tT[(size_t)sci[cc] * NH + j]);
        float tt = tm + trop_b[l * NH + j];

        const float4* AM  = (const float4*)(lf_amax + ((size_t)l * NH + j) * NP);
        const float4* BM  = (const float4*)(lf_bmax + ((size_t)l * NH + j) * NP);
        const float4* AN  = (const float4*)(lf_amin + ((size_t)l * NH + j) * NP);
        const float4* BMN = (const float4*)(lf_bmin + ((size_t)l * NH + j) * NP);
        float fmx = -1e30f, fmn = 1e30f;
#pragma unroll
        for (int q = 0; q < 2; q++) {
            float4 am = AM[q], bm = BM[q], an = AN[q], bn = BMN[q];
            fmx = fmaxf(fmx, fmaxf(fmaxf(tt * am.x + bm.x, tt * am.y + bm.y),
                                   fmaxf(tt * am.z + bm.z, tt * am.w + bm.w)));
            fmn = fminf(fmn, fminf(fminf(tt * an.x + bn.x, tt * an.y + bn.y),
                                   fminf(tt * an.z + bn.z, tt * an.w + bn.w)));
        }
        float a_ = sigmoidf_(lf_alpha[l * NH + j]);
        float trop_out = a_ * fmx + (1.0f - a_) * fmn;
        float cls_out = 0.5f * c * (1.0f + erff(c * 0.70710678118654752f));
        float gg = sigmoidf_(g);
        v[k] = g_h[row * NH + j] + gg * trop_out + (1.0f - gg) * cls_out;
        g_h[row * NH + j] = v[k];
    }
    __syncthreads();

    if (l < NL - 1) {
        ln_and_candidates(row, t, v[0], v[1], v[2], ln_g, ln_b, l + 1);
    } else {
        __shared__ float fr1[8], fr2[8], fbc[2];
        int lane = t & 31, wid = t >> 5;
        float s = v[0] + v[1] + v[2];
        float q = v[0] * v[0] + v[1] * v[1] + v[2] * v[2];
        for (int off = 16; off > 0; off >>= 1) {
            s += __shfl_down_sync(0xffffffffu, s, off);
            q += __shfl_down_sync(0xffffffffu, q, off);
        }
        if (lane == 0) { fr1[wid] = s; fr2[wid] = q; }
        __syncthreads();
        if (t == 0) {
            float ss = 0.f, qq = 0.f;
            for (int w = 0; w < 8; w++) { ss += fr1[w]; qq += fr2[w]; }
            float mu  = ss / (float)NH;
            float var = fmaxf(qq / (float)NH - mu * mu, 0.f);
            fbc[0] = mu; fbc[1] = rsqrtf(var + EPSV);
        }
        __syncthreads();
        float mu = fbc[0], inv = fbc[1];
        float d = ((v[0] - mu) * inv * out_g[t]       + out_b[t])       * head_w[t]
                + ((v[1] - mu) * inv * out_g[t + 256] + out_b[t + 256]) * head_w[t + 256]
                + ((v[2] - mu) * inv * out_g[t + 512] + out_b[t + 512]) * head_w[t + 512];
        for (int off = 16; off > 0; off >>= 1) d += __shfl_down_sync(0xffffffffu, d, off);
        __syncthreads();
        if (lane == 0) fr1[wid] = d;
        __syncthreads();
        if (t == 0) {
            float dd = 0.f;
            for (int w = 0; w < 8; w++) dd += fr1[w];
            out[row] = dd + head_b[0];
        }
    }
}

// ---------------- launch ----------------
extern "C" void kernel_launch(void* const* d_in, const int* in_sizes, int n_in,
                              void* d_out, int out_size) {
    const float* x        = (const float*)d_in[0];
    const float* w_in     = (const float*)d_in[1];
    const float* b_in     = (const float*)d_in[2];
    const float* ln_g     = (const float*)d_in[3];
    const float* ln_b     = (const float*)d_in[4];
    const float* trop_w   = (const float*)d_in[5];
    const float* trop_b   = (const float*)d_in[6];
    const float* lf_amax  = (const float*)d_in[7];
    const float* lf_bmax  = (const float*)d_in[8];
    const float* lf_amin  = (const float*)d_in[9];
    const float* lf_bmin  = (const float*)d_in[10];
    const float* lf_alpha = (const float*)d_in[11];
    const float* gate_w   = (const float*)d_in[12];
    const float* gate_b   = (const float*)d_in[13];
    const float* cls_w    = (const float*)d_in[14];
    const float* cls_b    = (const float*)d_in[15];
    const float* out_g    = (const float*)d_in[16];
    const float* out_b    = (const float*)d_in[17];
    const float* head_w   = (const float*)d_in[18];
    const float* head_b   = (const float*)d_in[19];
    float* out = (float*)d_out;

    cudaFuncSetAttribute(k_gemm_mma, cudaFuncAttributeMaxDynamicSharedMemorySize, SMEM_GEMM);

    k_prep<<<dim3(NH / 32, NH / 32, NL + 2 * NL), dim3(32, 8)>>>(trop_w, cls_w, gate_w);
    k_input<<<dim3(6, 32), 256>>>(x, w_in, b_in);
    k_ln0<<<NB, 256>>>(ln_g, ln_b);
    for (int l = 0; l < NL; l++) {
        k_gemm_mma<<<dim3(12, 4, 6), 256, SMEM_GEMM>>>(l);
        k_epi<<<NB, 256>>>(l, cls_b, gate_b, trop_b,
                           lf_amax, lf_bmax, lf_amin, lf_bmin, lf_alpha,
                           ln_g, ln_b, out_g, out_b, head_w, head_b, out);
    }
}